// round 1
// baseline (speedup 1.0000x reference)
#include <cuda_runtime.h>

#define BATCH 8
#define HEADS 16
#define NTOK  1024
#define DHEAD 64
#define EMB   1024
#define KDIM  1024

// ---- scratch (allocation-free rule: __device__ globals) ----
__device__ float g_q[BATCH*HEADS*NTOK*DHEAD];   // 32 MB, q pre-scaled
__device__ float g_k[BATCH*HEADS*NTOK*DHEAD];   // 32 MB
__device__ float g_v[BATCH*HEADS*NTOK*DHEAD];   // 32 MB
__device__ float g_ao[BATCH*NTOK*EMB];          // 32 MB attention output [b,n,e]

// ============================================================================
// GEMM: C[m,c] = sum_k A[m,k] * B[c,k]   (A: MxK row-major, B: CxK row-major)
// MODE 0: qkv  -> scatter into g_q/g_k/g_v (head layout), q *= 0.125
// MODE 1: proj -> A := g_ao, out[m,c] = acc + bias[c]
// 128x128x16 tiles, 256 threads, 8x8 microtiles.
// ============================================================================
template<int MODE>
__global__ __launch_bounds__(256) void gemm_kernel(
    const float* __restrict__ A, const float* __restrict__ B,
    const float* __restrict__ bias, float* __restrict__ C)
{
    __shared__ float As[16][132];
    __shared__ float Bs[16][132];

    const int t  = threadIdx.x;
    const int tx = t & 15, ty = t >> 4;
    const int m0 = blockIdx.y * 128;
    const int n0 = blockIdx.x * 128;

    const float* Ap = (MODE == 1 ? g_ao : A) + (size_t)m0 * KDIM;
    const float* Bp = B + (size_t)n0 * KDIM;

    const int r0  = t >> 2;           // 0..63
    const int kk0 = (t & 3) << 2;     // 0,4,8,12

    float4 a0, a1, b0, b1;
    a0 = *(const float4*)(Ap + (size_t)r0       * KDIM + kk0);
    a1 = *(const float4*)(Ap + (size_t)(r0+64)  * KDIM + kk0);
    b0 = *(const float4*)(Bp + (size_t)r0       * KDIM + kk0);
    b1 = *(const float4*)(Bp + (size_t)(r0+64)  * KDIM + kk0);

    float acc[8][8];
    #pragma unroll
    for (int i = 0; i < 8; i++)
        #pragma unroll
        for (int j = 0; j < 8; j++) acc[i][j] = 0.f;

    for (int k0 = 0; k0 < KDIM; k0 += 16) {
        __syncthreads();
        As[kk0+0][r0]    = a0.x; As[kk0+1][r0]    = a0.y; As[kk0+2][r0]    = a0.z; As[kk0+3][r0]    = a0.w;
        As[kk0+0][r0+64] = a1.x; As[kk0+1][r0+64] = a1.y; As[kk0+2][r0+64] = a1.z; As[kk0+3][r0+64] = a1.w;
        Bs[kk0+0][r0]    = b0.x; Bs[kk0+1][r0]    = b0.y; Bs[kk0+2][r0]    = b0.z; Bs[kk0+3][r0]    = b0.w;
        Bs[kk0+0][r0+64] = b1.x; Bs[kk0+1][r0+64] = b1.y; Bs[kk0+2][r0+64] = b1.z; Bs[kk0+3][r0+64] = b1.w;
        __syncthreads();

        if (k0 + 16 < KDIM) {
            const int kn = k0 + 16;
            a0 = *(const float4*)(Ap + (size_t)r0      * KDIM + kn + kk0);
            a1 = *(const float4*)(Ap + (size_t)(r0+64) * KDIM + kn + kk0);
            b0 = *(const float4*)(Bp + (size_t)r0      * KDIM + kn + kk0);
            b1 = *(const float4*)(Bp + (size_t)(r0+64) * KDIM + kn + kk0);
        }

        #pragma unroll
        for (int kk = 0; kk < 16; kk++) {
            float av[8], bv[8];
            *(float4*)&av[0] = *(const float4*)&As[kk][ty*8];
            *(float4*)&av[4] = *(const float4*)&As[kk][ty*8+4];
            *(float4*)&bv[0] = *(const float4*)&Bs[kk][tx*8];
            *(float4*)&bv[4] = *(const float4*)&Bs[kk][tx*8+4];
            #pragma unroll
            for (int i = 0; i < 8; i++)
                #pragma unroll
                for (int j = 0; j < 8; j++)
                    acc[i][j] = fmaf(av[i], bv[j], acc[i][j]);
        }
    }

    if (MODE == 0) {
        #pragma unroll
        for (int i = 0; i < 8; i++) {
            const int m  = m0 + ty*8 + i;
            const int bb = m >> 10, nn = m & 1023;
            #pragma unroll
            for (int jv = 0; jv < 2; jv++) {
                const int c    = n0 + tx*8 + jv*4;
                const int part = c >> 10;
                const int e    = c & 1023;
                const int h    = e >> 6, d = e & 63;
                const size_t off = ((size_t)((bb*HEADS + h)*NTOK + nn) << 6) + d;
                float4 v = make_float4(acc[i][jv*4+0], acc[i][jv*4+1],
                                       acc[i][jv*4+2], acc[i][jv*4+3]);
                if (part == 0) {
                    v.x *= 0.125f; v.y *= 0.125f; v.z *= 0.125f; v.w *= 0.125f;
                    *(float4*)&g_q[off] = v;
                } else if (part == 1) {
                    *(float4*)&g_k[off] = v;
                } else {
                    *(float4*)&g_v[off] = v;
                }
            }
        }
    } else {
        #pragma unroll
        for (int i = 0; i < 8; i++) {
            const int m = m0 + ty*8 + i;
            #pragma unroll
            for (int jv = 0; jv < 2; jv++) {
                const int c = n0 + tx*8 + jv*4;
                const float4 b4 = *(const float4*)&bias[c];
                float4 v = make_float4(acc[i][jv*4+0] + b4.x, acc[i][jv*4+1] + b4.y,
                                       acc[i][jv*4+2] + b4.z, acc[i][jv*4+3] + b4.w);
                *(float4*)&C[(size_t)m * EMB + c] = v;
            }
        }
    }
}

// ============================================================================
// Attention: one block = (b, h, 64-row query tile). Flash-style online softmax
// over 16 K-tiles of 64. Bias computed analytically: idx = |dx|*32 + |dy|.
// ============================================================================
#define SM_STRIDE 68
#define ATTN_SMEM_BYTES ((3*64*SM_STRIDE + 1024) * 4)

__global__ __launch_bounds__(256) void attn_kernel(const float* __restrict__ biases)
{
    extern __shared__ float sm[];
    float* Qt  = sm;                      // [64 d][64 i]  (transposed, stride 68)
    float* KV  = sm + 64*SM_STRIDE;       // K transposed [d][j] / V natural [j][d]
    float* Pt  = sm + 2*64*SM_STRIDE;     // P transposed [j][i]
    float* bsh = sm + 3*64*SM_STRIDE;     // bias row for this head [1024]

    const int t  = threadIdx.x;
    const int tx = t & 15, ty = t >> 4;
    const int qt = blockIdx.x, h = blockIdx.y, b = blockIdx.z;
    const int bh = b*HEADS + h;

    const float* qp  = g_q + ((size_t)bh*NTOK + qt*64) * DHEAD;
    const float* kpB = g_k + (size_t)bh*NTOK*DHEAD;
    const float* vpB = g_v + (size_t)bh*NTOK*DHEAD;

    // load Q transposed: Qt[d][i] = q[i][d]
    #pragma unroll
    for (int u = 0; u < 4; u++) {
        const int id = t + u*256;
        const int i = id >> 4, ds = (id & 15) << 2;
        const float4 v = *(const float4*)(qp + i*DHEAD + ds);
        Qt[(ds+0)*SM_STRIDE + i] = v.x;
        Qt[(ds+1)*SM_STRIDE + i] = v.y;
        Qt[(ds+2)*SM_STRIDE + i] = v.z;
        Qt[(ds+3)*SM_STRIDE + i] = v.w;
    }
    for (int id = t; id < 1024; id += 256) bsh[id] = biases[h*1024 + id];

    float m_run[4], l_run[4], o[4][4];
    int xq[4], yq[4];
    #pragma unroll
    for (int ii = 0; ii < 4; ii++) {
        m_run[ii] = -1e30f; l_run[ii] = 0.f;
        const int qi = qt*64 + ty*4 + ii;
        xq[ii] = qi >> 5; yq[ii] = qi & 31;
        #pragma unroll
        for (int dd = 0; dd < 4; dd++) o[ii][dd] = 0.f;
    }

    for (int kt = 0; kt < 16; kt++) {
        // load K tile transposed: KV[d][j] = k[j][d]
        const float* kp = kpB + (size_t)kt*64*DHEAD;
        #pragma unroll
        for (int u = 0; u < 4; u++) {
            const int id = t + u*256;
            const int j = id >> 4, ds = (id & 15) << 2;
            const float4 v = *(const float4*)(kp + j*DHEAD + ds);
            KV[(ds+0)*SM_STRIDE + j] = v.x;
            KV[(ds+1)*SM_STRIDE + j] = v.y;
            KV[(ds+2)*SM_STRIDE + j] = v.z;
            KV[(ds+3)*SM_STRIDE + j] = v.w;
        }
        __syncthreads();

        // S = Q @ K^T  (q already scaled)
        float s[4][4];
        #pragma unroll
        for (int ii = 0; ii < 4; ii++)
            #pragma unroll
            for (int jj = 0; jj < 4; jj++) s[ii][jj] = 0.f;
        #pragma unroll 8
        for (int d = 0; d < 64; d++) {
            const float4 aq = *(const float4*)&Qt[d*SM_STRIDE + ty*4];
            const float4 bk = *(const float4*)&KV[d*SM_STRIDE + tx*4];
            const float av[4] = {aq.x, aq.y, aq.z, aq.w};
            const float bv[4] = {bk.x, bk.y, bk.z, bk.w};
            #pragma unroll
            for (int ii = 0; ii < 4; ii++)
                #pragma unroll
                for (int jj = 0; jj < 4; jj++)
                    s[ii][jj] = fmaf(av[ii], bv[jj], s[ii][jj]);
        }

        // + bias (analytic idx), tile row max
        float tmax[4];
        #pragma unroll
        for (int ii = 0; ii < 4; ii++) {
            tmax[ii] = -1e30f;
            #pragma unroll
            for (int jj = 0; jj < 4; jj++) {
                const int kj = kt*64 + tx*4 + jj;
                int dx = xq[ii] - (kj >> 5); dx = dx < 0 ? -dx : dx;
                int dy = yq[ii] - (kj & 31); dy = dy < 0 ? -dy : dy;
                s[ii][jj] += bsh[dx*32 + dy];
                tmax[ii] = fmaxf(tmax[ii], s[ii][jj]);
            }
            #pragma unroll
            for (int off = 8; off >= 1; off >>= 1)
                tmax[ii] = fmaxf(tmax[ii], __shfl_xor_sync(0xffffffffu, tmax[ii], off, 16));
        }

        // online softmax update
        #pragma unroll
        for (int ii = 0; ii < 4; ii++) {
            const float mn  = fmaxf(m_run[ii], tmax[ii]);
            const float fac = __expf(m_run[ii] - mn);
            m_run[ii] = mn;
            l_run[ii] *= fac;
            #pragma unroll
            for (int dd = 0; dd < 4; dd++) o[ii][dd] *= fac;
        }
        #pragma unroll
        for (int ii = 0; ii < 4; ii++)
            #pragma unroll
            for (int jj = 0; jj < 4; jj++) {
                const float p = __expf(s[ii][jj] - m_run[ii]);
                l_run[ii] += p;
                Pt[(tx*4+jj)*SM_STRIDE + (ty*4+ii)] = p;
            }
        __syncthreads();   // Pt complete, K reads done -> KV reusable

        // load V tile natural: KV[j][d]
        const float* vp = vpB + (size_t)kt*64*DHEAD;
        #pragma unroll
        for (int u = 0; u < 4; u++) {
            const int id = t + u*256;
            const int j = id >> 4, ds = (id & 15) << 2;
            *(float4*)&KV[j*SM_STRIDE + ds] = *(const float4*)(vp + j*DHEAD + ds);
        }
        __syncthreads();

        // O += P @ V
        #pragma unroll 8
        for (int j = 0; j < 64; j++) {
            const float4 ap = *(const float4*)&Pt[j*SM_STRIDE + ty*4];
            const float4 vv = *(const float4*)&KV[j*SM_STRIDE + tx*4];
            const float av[4] = {ap.x, ap.y, ap.z, ap.w};
            const float bv[4] = {vv.x, vv.y, vv.z, vv.w};
            #pragma unroll
            for (int ii = 0; ii < 4; ii++)
                #pragma unroll
                for (int dd = 0; dd < 4; dd++)
                    o[ii][dd] = fmaf(av[ii], bv[dd], o[ii][dd]);
        }
        __syncthreads();   // before next iter overwrites KV / Pt
    }

    // epilogue: normalize, write [b, n, h*64+d]
    #pragma unroll
    for (int ii = 0; ii < 4; ii++) {
        float ls = l_run[ii];
        #pragma unroll
        for (int off = 8; off >= 1; off >>= 1)
            ls += __shfl_xor_sync(0xffffffffu, ls, off, 16);
        const float inv = 1.0f / ls;
        const int row = qt*64 + ty*4 + ii;
        float4 vo = make_float4(o[ii][0]*inv, o[ii][1]*inv, o[ii][2]*inv, o[ii][3]*inv);
        *(float4*)&g_ao[((size_t)(b*NTOK + row)) * EMB + h*64 + tx*4] = vo;
    }
}

// ============================================================================
extern "C" void kernel_launch(void* const* d_in, const int* in_sizes, int n_in,
                              void* d_out, int out_size)
{
    const float* x     = (const float*)d_in[0];
    const float* Wqkv  = (const float*)d_in[1];
    const float* ab    = (const float*)d_in[2];
    // d_in[3] = bias_idxs : not needed (idx = |dx|*32 + |dy| analytically)
    const float* Wout  = (const float*)d_in[4];
    const float* bout  = (const float*)d_in[5];
    float* out = (float*)d_out;

    cudaFuncSetAttribute(attn_kernel, cudaFuncAttributeMaxDynamicSharedMemorySize,
                         ATTN_SMEM_BYTES);

    gemm_kernel<0><<<dim3(3072/128, 8192/128), 256>>>(x, Wqkv, nullptr, nullptr);
    attn_kernel<<<dim3(NTOK/64, HEADS, BATCH), 256, ATTN_SMEM_BYTES>>>(ab);
    gemm_kernel<1><<<dim3(1024/128, 8192/128), 256>>>(nullptr, Wout, bout, out);
}

// round 2
// speedup vs baseline: 1.5450x; 1.5450x over previous
#include <cuda_runtime.h>
#include <cuda_bf16.h>
#include <cstdint>

#define BATCH 8
#define HEADS 16
#define NTOK  1024
#define DHEAD 64
#define EMB   1024
#define KD    1024

// ---- scratch (allocation-free rule: __device__ globals) ----
__device__ float g_q[BATCH*HEADS*NTOK*DHEAD];   // q pre-scaled
__device__ float g_k[BATCH*HEADS*NTOK*DHEAD];
__device__ float g_v[BATCH*HEADS*NTOK*DHEAD];

// split-bf16 limb buffers
__device__ __nv_bfloat16 g_xh [8192*1024];
__device__ __nv_bfloat16 g_xl [8192*1024];
__device__ __nv_bfloat16 g_wqh[3072*1024];
__device__ __nv_bfloat16 g_wql[3072*1024];
__device__ __nv_bfloat16 g_woh[1024*1024];
__device__ __nv_bfloat16 g_wol[1024*1024];
__device__ __nv_bfloat16 g_aoh[8192*1024];
__device__ __nv_bfloat16 g_aol[8192*1024];

// ---------------------------------------------------------------------------
__device__ __forceinline__ uint32_t smem_u32(const void* p) {
    return (uint32_t)__cvta_generic_to_shared(p);
}
__device__ __forceinline__ uint32_t pack_bf2(float x, float y) {
    __nv_bfloat162 t = __floats2bfloat162_rn(x, y);
    return *reinterpret_cast<uint32_t*>(&t);
}
__device__ __forceinline__ void ldsm_x4(uint32_t* r, uint32_t addr) {
    asm volatile("ldmatrix.sync.aligned.m8n8.x4.shared.b16 {%0,%1,%2,%3},[%4];"
                 : "=r"(r[0]), "=r"(r[1]), "=r"(r[2]), "=r"(r[3]) : "r"(addr));
}
__device__ __forceinline__ void mma_bf16(float* c, const uint32_t* a, const uint32_t* b) {
    asm volatile("mma.sync.aligned.m16n8k16.row.col.f32.bf16.bf16.f32 "
                 "{%0,%1,%2,%3},{%4,%5,%6,%7},{%8,%9},{%0,%1,%2,%3};"
                 : "+f"(c[0]), "+f"(c[1]), "+f"(c[2]), "+f"(c[3])
                 : "r"(a[0]), "r"(a[1]), "r"(a[2]), "r"(a[3]), "r"(b[0]), "r"(b[1]));
}

// ---------------------------------------------------------------------------
// fp32 -> (hi, lo) bf16 limb conversion.  which: 0=x, 1=Wqkv, 2=Wout
// ---------------------------------------------------------------------------
__global__ __launch_bounds__(256) void convert_kernel(const float* __restrict__ src,
                                                      int which, int n)
{
    int i = (blockIdx.x * 256 + threadIdx.x) * 4;
    if (i >= n) return;
    __nv_bfloat16 *hi, *lo;
    if (which == 0)      { hi = g_xh;  lo = g_xl;  }
    else if (which == 1) { hi = g_wqh; lo = g_wql; }
    else                 { hi = g_woh; lo = g_wol; }

    float4 v = *(const float4*)(src + i);
    float h0 = __bfloat162float(__float2bfloat16(v.x));
    float h1 = __bfloat162float(__float2bfloat16(v.y));
    float h2 = __bfloat162float(__float2bfloat16(v.z));
    float h3 = __bfloat162float(__float2bfloat16(v.w));
    uint2 ph, pl;
    ph.x = pack_bf2(v.x, v.y);
    ph.y = pack_bf2(v.z, v.w);
    pl.x = pack_bf2(v.x - h0, v.y - h1);
    pl.y = pack_bf2(v.z - h2, v.w - h3);
    *(uint2*)&hi[i] = ph;
    *(uint2*)&lo[i] = pl;
}

// ---------------------------------------------------------------------------
// Split-bf16 tensor-core GEMM: C[m,c] = sum_k A(m,k)*B(c,k)
//   = Ah*Bh + Ah*Bl + Al*Bh  (3x mma.sync bf16, fp32 accum)
// Block tile 128x128, 512 threads (16 warps as 4Mx4N), warp tile 32x32, K-step 32.
// MODE 0: A=x limbs, B=Wqkv limbs -> scatter into g_q/g_k/g_v (q *= 0.125)
// MODE 1: A=attn-out limbs, B=Wout limbs -> +bias -> C
// ---------------------------------------------------------------------------
#define LDS 40   // smem row stride (bf16 elems): 80B, conflict-free mod 128

template<int MODE>
__global__ __launch_bounds__(512) void mma_gemm(const float* __restrict__ bias,
                                                float* __restrict__ C)
{
    __shared__ alignas(16) __nv_bfloat16 As[2 * 128 * LDS];
    __shared__ alignas(16) __nv_bfloat16 Bs[2 * 128 * LDS];

    const int t    = threadIdx.x;
    const int lane = t & 31;
    const int wid  = t >> 5;
    const int wm   = (wid & 3) << 5;   // warp M offset (0..96)
    const int wn   = (wid >> 2) << 5;  // warp N offset (0..96)
    const int m0   = blockIdx.y * 128;
    const int n0   = blockIdx.x * 128;

    const __nv_bfloat16* Ah = (MODE == 0) ? g_xh  : g_aoh;
    const __nv_bfloat16* Al = (MODE == 0) ? g_xl  : g_aol;
    const __nv_bfloat16* Bh = (MODE == 0) ? g_wqh : g_woh;
    const __nv_bfloat16* Bl = (MODE == 0) ? g_wql : g_wol;

    // global load mapping: thread -> (row 0..127, 16B chunk 0..3), both limbs
    const int lrow = t >> 2;
    const int lch  = (t & 3) << 3;               // element offset within row
    const __nv_bfloat16* pAh = Ah + (size_t)(m0 + lrow) * KD + lch;
    const __nv_bfloat16* pAl = Al + (size_t)(m0 + lrow) * KD + lch;
    const __nv_bfloat16* pBh = Bh + (size_t)(n0 + lrow) * KD + lch;
    const __nv_bfloat16* pBl = Bl + (size_t)(n0 + lrow) * KD + lch;

    const int soff = lrow * LDS + lch;           // smem elem offset (limb plane 0)

    uint4 ra0 = *(const uint4*)pAh;
    uint4 ra1 = *(const uint4*)pAl;
    uint4 rb0 = *(const uint4*)pBh;
    uint4 rb1 = *(const uint4*)pBl;

    // ldmatrix lane addressing (element offsets)
    const int a_r = wm + (lane & 15);
    const int a_c = (lane >> 4) << 3;
    const int b_r = wn + ((lane >> 4) << 3) + (lane & 7);
    const int b_c = ((lane >> 3) & 1) << 3;
    const uint32_t sA = smem_u32(As);
    const uint32_t sB = smem_u32(Bs);

    float c[2][4][4];
    #pragma unroll
    for (int mt = 0; mt < 2; mt++)
        #pragma unroll
        for (int nt = 0; nt < 4; nt++)
            #pragma unroll
            for (int q = 0; q < 4; q++) c[mt][nt][q] = 0.f;

    for (int k0 = 0; k0 < KD; k0 += 32) {
        __syncthreads();
        *(uint4*)&As[soff]            = ra0;
        *(uint4*)&As[128 * LDS + soff] = ra1;
        *(uint4*)&Bs[soff]            = rb0;
        *(uint4*)&Bs[128 * LDS + soff] = rb1;
        __syncthreads();

        if (k0 + 32 < KD) {
            pAh += 32; pAl += 32; pBh += 32; pBl += 32;
            ra0 = *(const uint4*)pAh;
            ra1 = *(const uint4*)pAl;
            rb0 = *(const uint4*)pBh;
            rb1 = *(const uint4*)pBl;
        }

        #pragma unroll
        for (int kk = 0; kk < 32; kk += 16) {
            uint32_t ah[2][4], al[2][4], bh[2][4], bl[2][4];
            #pragma unroll
            for (int mt = 0; mt < 2; mt++) {
                ldsm_x4(ah[mt], sA + (uint32_t)(((a_r + mt * 16)       * LDS + kk + a_c) * 2));
                ldsm_x4(al[mt], sA + (uint32_t)(((128 + a_r + mt * 16) * LDS + kk + a_c) * 2));
            }
            #pragma unroll
            for (int pr = 0; pr < 2; pr++) {
                ldsm_x4(bh[pr], sB + (uint32_t)(((b_r + pr * 16)       * LDS + kk + b_c) * 2));
                ldsm_x4(bl[pr], sB + (uint32_t)(((128 + b_r + pr * 16) * LDS + kk + b_c) * 2));
            }
            #pragma unroll
            for (int mt = 0; mt < 2; mt++)
                #pragma unroll
                for (int nt = 0; nt < 4; nt++) {
                    uint32_t* B0 = &bh[nt >> 1][(nt & 1) * 2];
                    uint32_t* B1 = &bl[nt >> 1][(nt & 1) * 2];
                    mma_bf16(c[mt][nt], ah[mt], B0);
                    mma_bf16(c[mt][nt], ah[mt], B1);
                    mma_bf16(c[mt][nt], al[mt], B0);
                }
        }
    }

    // ---- epilogue ----
    #pragma unroll
    for (int mt = 0; mt < 2; mt++) {
        #pragma unroll
        for (int half = 0; half < 2; half++) {
            const int m  = m0 + wm + mt * 16 + (lane >> 2) + half * 8;
            if (MODE == 0) {
                const int bb = m >> 10, nn = m & 1023;
                #pragma unroll
                for (int nt = 0; nt < 4; nt++) {
                    const int cg   = n0 + wn + nt * 8 + (lane & 3) * 2;
                    const int part = cg >> 10;
                    const int e    = cg & 1023;
                    const int hh   = e >> 6, d = e & 63;
                    const size_t off = ((size_t)((bb * HEADS + hh) * NTOK + nn) << 6) + d;
                    float2 v = make_float2(c[mt][nt][half * 2], c[mt][nt][half * 2 + 1]);
                    if (part == 0) {
                        v.x *= 0.125f; v.y *= 0.125f;
                        *(float2*)&g_q[off] = v;
                    } else if (part == 1) {
                        *(float2*)&g_k[off] = v;
                    } else {
                        *(float2*)&g_v[off] = v;
                    }
                }
            } else {
                #pragma unroll
                for (int nt = 0; nt < 4; nt++) {
                    const int cg = n0 + wn + nt * 8 + (lane & 3) * 2;
                    const float2 b2 = *(const float2*)&bias[cg];
                    float2 v = make_float2(c[mt][nt][half * 2] + b2.x,
                                           c[mt][nt][half * 2 + 1] + b2.y);
                    *(float2*)&C[(size_t)m * EMB + cg] = v;
                }
            }
        }
    }
}

// ============================================================================
// Attention: one block = (b, h, 64-row query tile). Flash-style online softmax
// over 16 K-tiles of 64. Bias computed analytically: idx = |dx|*32 + |dy|.
// Epilogue writes split-bf16 limbs for the out-projection.
// ============================================================================
#define SM_STRIDE 68
#define ATTN_SMEM_BYTES ((3*64*SM_STRIDE + 1024) * 4)

__global__ __launch_bounds__(256) void attn_kernel(const float* __restrict__ biases)
{
    extern __shared__ float sm[];
    float* Qt  = sm;                      // [64 d][64 i]  (transposed, stride 68)
    float* KV  = sm + 64*SM_STRIDE;       // K transposed [d][j] / V natural [j][d]
    float* Pt  = sm + 2*64*SM_STRIDE;     // P transposed [j][i]
    float* bsh = sm + 3*64*SM_STRIDE;     // bias row for this head [1024]

    const int t  = threadIdx.x;
    const int tx = t & 15, ty = t >> 4;
    const int qt = blockIdx.x, h = blockIdx.y, b = blockIdx.z;
    const int bh = b*HEADS + h;

    const float* qp  = g_q + ((size_t)bh*NTOK + qt*64) * DHEAD;
    const float* kpB = g_k + (size_t)bh*NTOK*DHEAD;
    const float* vpB = g_v + (size_t)bh*NTOK*DHEAD;

    #pragma unroll
    for (int u = 0; u < 4; u++) {
        const int id = t + u*256;
        const int i = id >> 4, ds = (id & 15) << 2;
        const float4 v = *(const float4*)(qp + i*DHEAD + ds);
        Qt[(ds+0)*SM_STRIDE + i] = v.x;
        Qt[(ds+1)*SM_STRIDE + i] = v.y;
        Qt[(ds+2)*SM_STRIDE + i] = v.z;
        Qt[(ds+3)*SM_STRIDE + i] = v.w;
    }
    for (int id = t; id < 1024; id += 256) bsh[id] = biases[h*1024 + id];

    float m_run[4], l_run[4], o[4][4];
    int xq[4], yq[4];
    #pragma unroll
    for (int ii = 0; ii < 4; ii++) {
        m_run[ii] = -1e30f; l_run[ii] = 0.f;
        const int qi = qt*64 + ty*4 + ii;
        xq[ii] = qi >> 5; yq[ii] = qi & 31;
        #pragma unroll
        for (int dd = 0; dd < 4; dd++) o[ii][dd] = 0.f;
    }

    for (int kt = 0; kt < 16; kt++) {
        const float* kp = kpB + (size_t)kt*64*DHEAD;
        #pragma unroll
        for (int u = 0; u < 4; u++) {
            const int id = t + u*256;
            const int j = id >> 4, ds = (id & 15) << 2;
            const float4 v = *(const float4*)(kp + j*DHEAD + ds);
            KV[(ds+0)*SM_STRIDE + j] = v.x;
            KV[(ds+1)*SM_STRIDE + j] = v.y;
            KV[(ds+2)*SM_STRIDE + j] = v.z;
            KV[(ds+3)*SM_STRIDE + j] = v.w;
        }
        __syncthreads();

        float s[4][4];
        #pragma unroll
        for (int ii = 0; ii < 4; ii++)
            #pragma unroll
            for (int jj = 0; jj < 4; jj++) s[ii][jj] = 0.f;
        #pragma unroll 8
        for (int d = 0; d < 64; d++) {
            const float4 aq = *(const float4*)&Qt[d*SM_STRIDE + ty*4];
            const float4 bk = *(const float4*)&KV[d*SM_STRIDE + tx*4];
            const float av[4] = {aq.x, aq.y, aq.z, aq.w};
            const float bv[4] = {bk.x, bk.y, bk.z, bk.w};
            #pragma unroll
            for (int ii = 0; ii < 4; ii++)
                #pragma unroll
                for (int jj = 0; jj < 4; jj++)
                    s[ii][jj] = fmaf(av[ii], bv[jj], s[ii][jj]);
        }

        float tmax[4];
        #pragma unroll
        for (int ii = 0; ii < 4; ii++) {
            tmax[ii] = -1e30f;
            #pragma unroll
            for (int jj = 0; jj < 4; jj++) {
                const int kj = kt*64 + tx*4 + jj;
                int dx = xq[ii] - (kj >> 5); dx = dx < 0 ? -dx : dx;
                int dy = yq[ii] - (kj & 31); dy = dy < 0 ? -dy : dy;
                s[ii][jj] += bsh[dx*32 + dy];
                tmax[ii] = fmaxf(tmax[ii], s[ii][jj]);
            }
            #pragma unroll
            for (int off = 8; off >= 1; off >>= 1)
                tmax[ii] = fmaxf(tmax[ii], __shfl_xor_sync(0xffffffffu, tmax[ii], off, 16));
        }

        #pragma unroll
        for (int ii = 0; ii < 4; ii++) {
            const float mn  = fmaxf(m_run[ii], tmax[ii]);
            const float fac = __expf(m_run[ii] - mn);
            m_run[ii] = mn;
            l_run[ii] *= fac;
            #pragma unroll
            for (int dd = 0; dd < 4; dd++) o[ii][dd] *= fac;
        }
        #pragma unroll
        for (int ii = 0; ii < 4; ii++)
            #pragma unroll
            for (int jj = 0; jj < 4; jj++) {
                const float p = __expf(s[ii][jj] - m_run[ii]);
                l_run[ii] += p;
                Pt[(tx*4+jj)*SM_STRIDE + (ty*4+ii)] = p;
            }
        __syncthreads();

        const float* vp = vpB + (size_t)kt*64*DHEAD;
        #pragma unroll
        for (int u = 0; u < 4; u++) {
            const int id = t + u*256;
            const int j = id >> 4, ds = (id & 15) << 2;
            *(float4*)&KV[j*SM_STRIDE + ds] = *(const float4*)(vp + j*DHEAD + ds);
        }
        __syncthreads();

        #pragma unroll 8
        for (int j = 0; j < 64; j++) {
            const float4 ap = *(const float4*)&Pt[j*SM_STRIDE + ty*4];
            const float4 vv = *(const float4*)&KV[j*SM_STRIDE + tx*4];
            const float av[4] = {ap.x, ap.y, ap.z, ap.w};
            const float bv[4] = {vv.x, vv.y, vv.z, vv.w};
            #pragma unroll
            for (int ii = 0; ii < 4; ii++)
                #pragma unroll
                for (int dd = 0; dd < 4; dd++)
                    o[ii][dd] = fmaf(av[ii], bv[dd], o[ii][dd]);
        }
        __syncthreads();
    }

    // epilogue: normalize, write split-bf16 limbs [b, n, h*64+d]
    #pragma unroll
    for (int ii = 0; ii < 4; ii++) {
        float ls = l_run[ii];
        #pragma unroll
        for (int off = 8; off >= 1; off >>= 1)
            ls += __shfl_xor_sync(0xffffffffu, ls, off, 16);
        const float inv = 1.0f / ls;
        const int row = qt*64 + ty*4 + ii;
        const float f0 = o[ii][0]*inv, f1 = o[ii][1]*inv;
        const float f2 = o[ii][2]*inv, f3 = o[ii][3]*inv;
        const float r0 = f0 - __bfloat162float(__float2bfloat16(f0));
        const float r1 = f1 - __bfloat162float(__float2bfloat16(f1));
        const float r2 = f2 - __bfloat162float(__float2bfloat16(f2));
        const float r3 = f3 - __bfloat162float(__float2bfloat16(f3));
        uint2 ph, pl;
        ph.x = pack_bf2(f0, f1); ph.y = pack_bf2(f2, f3);
        pl.x = pack_bf2(r0, r1); pl.y = pack_bf2(r2, r3);
        const size_t idx = ((size_t)(b*NTOK + row)) * EMB + h*64 + tx*4;
        *(uint2*)&g_aoh[idx] = ph;
        *(uint2*)&g_aol[idx] = pl;
    }
}

// ============================================================================
extern "C" void kernel_launch(void* const* d_in, const int* in_sizes, int n_in,
                              void* d_out, int out_size)
{
    const float* x     = (const float*)d_in[0];
    const float* Wqkv  = (const float*)d_in[1];
    const float* ab    = (const float*)d_in[2];
    // d_in[3] = bias_idxs : not needed (idx = |dx|*32 + |dy| analytically)
    const float* Wout  = (const float*)d_in[4];
    const float* bout  = (const float*)d_in[5];
    float* out = (float*)d_out;

    cudaFuncSetAttribute(attn_kernel, cudaFuncAttributeMaxDynamicSharedMemorySize,
                         ATTN_SMEM_BYTES);

    convert_kernel<<<8192*1024/1024, 256>>>(x,    0, 8192*1024);
    convert_kernel<<<3072*1024/1024, 256>>>(Wqkv, 1, 3072*1024);
    convert_kernel<<<1024*1024/1024, 256>>>(Wout, 2, 1024*1024);

    mma_gemm<0><<<dim3(3072/128, 8192/128), 512>>>(nullptr, nullptr);
    attn_kernel<<<dim3(NTOK/64, HEADS, BATCH), 256, ATTN_SMEM_BYTES>>>(ab);
    mma_gemm<1><<<dim3(1024/128, 8192/128), 512>>>(bout, out);
}

// round 3
// speedup vs baseline: 2.5395x; 1.6437x over previous
#include <cuda_runtime.h>
#include <cuda_bf16.h>
#include <cstdint>

#define BATCH 8
#define HEADS 16
#define NTOK  1024
#define DHEAD 64
#define EMB   1024
#define KD    1024

// ---- scratch (allocation-free rule: __device__ globals) ----
// q/k/v as bf16 hi/lo limb planes, layout [b,h,n,d]
__device__ __nv_bfloat16 g_qh[BATCH*HEADS*NTOK*DHEAD];
__device__ __nv_bfloat16 g_ql[BATCH*HEADS*NTOK*DHEAD];
__device__ __nv_bfloat16 g_kh[BATCH*HEADS*NTOK*DHEAD];
__device__ __nv_bfloat16 g_kl[BATCH*HEADS*NTOK*DHEAD];
__device__ __nv_bfloat16 g_vh[BATCH*HEADS*NTOK*DHEAD];
__device__ __nv_bfloat16 g_vl[BATCH*HEADS*NTOK*DHEAD];

// split-bf16 limb buffers for dense GEMMs
__device__ __nv_bfloat16 g_xh [8192*1024];
__device__ __nv_bfloat16 g_xl [8192*1024];
__device__ __nv_bfloat16 g_wqh[3072*1024];
__device__ __nv_bfloat16 g_wql[3072*1024];
__device__ __nv_bfloat16 g_woh[1024*1024];
__device__ __nv_bfloat16 g_wol[1024*1024];
__device__ __nv_bfloat16 g_aoh[8192*1024];
__device__ __nv_bfloat16 g_aol[8192*1024];

// ---------------------------------------------------------------------------
__device__ __forceinline__ uint32_t smem_u32(const void* p) {
    return (uint32_t)__cvta_generic_to_shared(p);
}
__device__ __forceinline__ uint32_t pack_bf2(float x, float y) {
    __nv_bfloat162 t = __floats2bfloat162_rn(x, y);
    return *reinterpret_cast<uint32_t*>(&t);
}
__device__ __forceinline__ void split2(float x, float y, uint32_t& hi, uint32_t& lo) {
    float hx = __bfloat162float(__float2bfloat16(x));
    float hy = __bfloat162float(__float2bfloat16(y));
    hi = pack_bf2(x, y);
    lo = pack_bf2(x - hx, y - hy);
}
__device__ __forceinline__ void ldsm_x4(uint32_t* r, uint32_t addr) {
    asm volatile("ldmatrix.sync.aligned.m8n8.x4.shared.b16 {%0,%1,%2,%3},[%4];"
                 : "=r"(r[0]), "=r"(r[1]), "=r"(r[2]), "=r"(r[3]) : "r"(addr));
}
__device__ __forceinline__ void ldsm_x4_t(uint32_t* r, uint32_t addr) {
    asm volatile("ldmatrix.sync.aligned.m8n8.x4.trans.shared.b16 {%0,%1,%2,%3},[%4];"
                 : "=r"(r[0]), "=r"(r[1]), "=r"(r[2]), "=r"(r[3]) : "r"(addr));
}
__device__ __forceinline__ void mma_bf16(float* c, const uint32_t* a, const uint32_t* b) {
    asm volatile("mma.sync.aligned.m16n8k16.row.col.f32.bf16.bf16.f32 "
                 "{%0,%1,%2,%3},{%4,%5,%6,%7},{%8,%9},{%0,%1,%2,%3};"
                 : "+f"(c[0]), "+f"(c[1]), "+f"(c[2]), "+f"(c[3])
                 : "r"(a[0]), "r"(a[1]), "r"(a[2]), "r"(a[3]), "r"(b[0]), "r"(b[1]));
}
__device__ __forceinline__ void cp16(uint32_t dst, const void* src) {
    asm volatile("cp.async.ca.shared.global [%0],[%1],16;" :: "r"(dst), "l"(src));
}
__device__ __forceinline__ void cp_commit() { asm volatile("cp.async.commit_group;"); }
__device__ __forceinline__ void cp_wait0() { asm volatile("cp.async.wait_group 0;"); }
__device__ __forceinline__ void cp_wait1() { asm volatile("cp.async.wait_group 1;"); }

// ---------------------------------------------------------------------------
// fp32 -> (hi, lo) bf16 limb conversion.  which: 0=x, 1=Wqkv, 2=Wout
// ---------------------------------------------------------------------------
__global__ __launch_bounds__(256) void convert_kernel(const float* __restrict__ src,
                                                      int which, int n)
{
    int i = (blockIdx.x * 256 + threadIdx.x) * 4;
    if (i >= n) return;
    __nv_bfloat16 *hi, *lo;
    if (which == 0)      { hi = g_xh;  lo = g_xl;  }
    else if (which == 1) { hi = g_wqh; lo = g_wql; }
    else                 { hi = g_woh; lo = g_wol; }

    float4 v = *(const float4*)(src + i);
    uint2 ph, pl;
    split2(v.x, v.y, ph.x, pl.x);
    split2(v.z, v.w, ph.y, pl.y);
    *(uint2*)&hi[i] = ph;
    *(uint2*)&lo[i] = pl;
}

// ---------------------------------------------------------------------------
// Split-bf16 tensor-core GEMM: C[m,c] = sum_k A(m,k)*B(c,k)
// MODE 0: A=x limbs, B=Wqkv limbs -> scatter limb planes g_q*/g_k*/g_v* (q*=0.125)
// MODE 1: A=attn-out limbs, B=Wout limbs -> +bias -> C (fp32)
// ---------------------------------------------------------------------------
#define LDS 40

template<int MODE>
__global__ __launch_bounds__(512) void mma_gemm(const float* __restrict__ bias,
                                                float* __restrict__ C)
{
    __shared__ alignas(16) __nv_bfloat16 As[2 * 128 * LDS];
    __shared__ alignas(16) __nv_bfloat16 Bs[2 * 128 * LDS];

    const int t    = threadIdx.x;
    const int lane = t & 31;
    const int wid  = t >> 5;
    const int wm   = (wid & 3) << 5;
    const int wn   = (wid >> 2) << 5;
    const int m0   = blockIdx.y * 128;
    const int n0   = blockIdx.x * 128;

    const __nv_bfloat16* Ah = (MODE == 0) ? g_xh  : g_aoh;
    const __nv_bfloat16* Al = (MODE == 0) ? g_xl  : g_aol;
    const __nv_bfloat16* Bh = (MODE == 0) ? g_wqh : g_woh;
    const __nv_bfloat16* Bl = (MODE == 0) ? g_wql : g_wol;

    const int lrow = t >> 2;
    const int lch  = (t & 3) << 3;
    const __nv_bfloat16* pAh = Ah + (size_t)(m0 + lrow) * KD + lch;
    const __nv_bfloat16* pAl = Al + (size_t)(m0 + lrow) * KD + lch;
    const __nv_bfloat16* pBh = Bh + (size_t)(n0 + lrow) * KD + lch;
    const __nv_bfloat16* pBl = Bl + (size_t)(n0 + lrow) * KD + lch;

    const int soff = lrow * LDS + lch;

    uint4 ra0 = *(const uint4*)pAh;
    uint4 ra1 = *(const uint4*)pAl;
    uint4 rb0 = *(const uint4*)pBh;
    uint4 rb1 = *(const uint4*)pBl;

    const int a_r = wm + (lane & 15);
    const int a_c = (lane >> 4) << 3;
    const int b_r = wn + ((lane >> 4) << 3) + (lane & 7);
    const int b_c = ((lane >> 3) & 1) << 3;
    const uint32_t sA = smem_u32(As);
    const uint32_t sB = smem_u32(Bs);

    float c[2][4][4];
    #pragma unroll
    for (int mt = 0; mt < 2; mt++)
        #pragma unroll
        for (int nt = 0; nt < 4; nt++)
            #pragma unroll
            for (int q = 0; q < 4; q++) c[mt][nt][q] = 0.f;

    for (int k0 = 0; k0 < KD; k0 += 32) {
        __syncthreads();
        *(uint4*)&As[soff]             = ra0;
        *(uint4*)&As[128 * LDS + soff] = ra1;
        *(uint4*)&Bs[soff]             = rb0;
        *(uint4*)&Bs[128 * LDS + soff] = rb1;
        __syncthreads();

        if (k0 + 32 < KD) {
            pAh += 32; pAl += 32; pBh += 32; pBl += 32;
            ra0 = *(const uint4*)pAh;
            ra1 = *(const uint4*)pAl;
            rb0 = *(const uint4*)pBh;
            rb1 = *(const uint4*)pBl;
        }

        #pragma unroll
        for (int kk = 0; kk < 32; kk += 16) {
            uint32_t ah[2][4], al[2][4], bh[2][4], bl[2][4];
            #pragma unroll
            for (int mt = 0; mt < 2; mt++) {
                ldsm_x4(ah[mt], sA + (uint32_t)(((a_r + mt * 16)       * LDS + kk + a_c) * 2));
                ldsm_x4(al[mt], sA + (uint32_t)(((128 + a_r + mt * 16) * LDS + kk + a_c) * 2));
            }
            #pragma unroll
            for (int pr = 0; pr < 2; pr++) {
                ldsm_x4(bh[pr], sB + (uint32_t)(((b_r + pr * 16)       * LDS + kk + b_c) * 2));
                ldsm_x4(bl[pr], sB + (uint32_t)(((128 + b_r + pr * 16) * LDS + kk + b_c) * 2));
            }
            #pragma unroll
            for (int mt = 0; mt < 2; mt++)
                #pragma unroll
                for (int nt = 0; nt < 4; nt++) {
                    uint32_t* B0 = &bh[nt >> 1][(nt & 1) * 2];
                    uint32_t* B1 = &bl[nt >> 1][(nt & 1) * 2];
                    mma_bf16(c[mt][nt], ah[mt], B0);
                    mma_bf16(c[mt][nt], ah[mt], B1);
                    mma_bf16(c[mt][nt], al[mt], B0);
                }
        }
    }

    #pragma unroll
    for (int mt = 0; mt < 2; mt++) {
        #pragma unroll
        for (int half = 0; half < 2; half++) {
            const int m = m0 + wm + mt * 16 + (lane >> 2) + half * 8;
            if (MODE == 0) {
                const int bb = m >> 10, nn = m & 1023;
                #pragma unroll
                for (int nt = 0; nt < 4; nt++) {
                    const int cg   = n0 + wn + nt * 8 + (lane & 3) * 2;
                    const int part = cg >> 10;
                    const int e    = cg & 1023;
                    const int hh   = e >> 6, d = e & 63;
                    const size_t off = ((size_t)((bb * HEADS + hh) * NTOK + nn) << 6) + d;
                    float vx = c[mt][nt][half * 2], vy = c[mt][nt][half * 2 + 1];
                    uint32_t hi, lo;
                    if (part == 0) {
                        vx *= 0.125f; vy *= 0.125f;
                        split2(vx, vy, hi, lo);
                        *(uint32_t*)&g_qh[off] = hi; *(uint32_t*)&g_ql[off] = lo;
                    } else if (part == 1) {
                        split2(vx, vy, hi, lo);
                        *(uint32_t*)&g_kh[off] = hi; *(uint32_t*)&g_kl[off] = lo;
                    } else {
                        split2(vx, vy, hi, lo);
                        *(uint32_t*)&g_vh[off] = hi; *(uint32_t*)&g_vl[off] = lo;
                    }
                }
            } else {
                #pragma unroll
                for (int nt = 0; nt < 4; nt++) {
                    const int cg = n0 + wn + nt * 8 + (lane & 3) * 2;
                    const float2 b2 = *(const float2*)&bias[cg];
                    float2 v = make_float2(c[mt][nt][half * 2] + b2.x,
                                           c[mt][nt][half * 2 + 1] + b2.y);
                    *(float2*)&C[(size_t)m * EMB + cg] = v;
                }
            }
        }
    }
}

// ============================================================================
// Tensor-core flash attention, split-bf16 limbs everywhere.
// Block = 128 queries (8 warps x m16), loop over 16 key tiles of 64.
// smem: [2 bufs][4 planes: Khi,Klo,Vhi,Vlo][64 rows][72 bf16] + bias[1024] f32
// ============================================================================
#define ASTR 72
#define PLANE_B (64 * ASTR * 2)          // bytes per plane
#define ATTN_SMEM (2 * 4 * 64 * ASTR * 2 + 1024 * 4)

__global__ __launch_bounds__(256) void attn_mma(const float* __restrict__ biases)
{
    extern __shared__ __nv_bfloat16 smem[];
    float* s_bias = (float*)(smem + 2 * 4 * 64 * ASTR);

    const int t = threadIdx.x, lane = t & 31, w = t >> 5;
    const int qt = blockIdx.x, h = blockIdx.y, b = blockIdx.z;
    const int bh = b * HEADS + h;
    const int q0 = qt * 128;
    const int rw = w * 16;

    for (int i = t; i < 1024; i += 256) s_bias[i] = biases[h * 1024 + i];

    // ---- Q fragment preload (hi, lo limbs), staged through smem ----
    uint32_t qh[4][4], ql[4][4];
    const uint32_t qAddr = smem_u32(smem) + ((rw + (lane & 15)) * ASTR + ((lane >> 4) << 3)) * 2;
    {
        const __nv_bfloat16* qsrc = g_qh + ((size_t)bh * NTOK + q0) * 64;
        #pragma unroll
        for (int u = 0; u < 4; u++) {
            const int id = t + u * 256, r = id >> 3, ch = (id & 7) * 8;
            cp16(smem_u32(smem + r * ASTR + ch), qsrc + (size_t)r * 64 + ch);
        }
        cp_commit(); cp_wait0(); __syncthreads();
        #pragma unroll
        for (int kk = 0; kk < 4; kk++) ldsm_x4(qh[kk], qAddr + kk * 32);
        __syncthreads();

        qsrc = g_ql + ((size_t)bh * NTOK + q0) * 64;
        #pragma unroll
        for (int u = 0; u < 4; u++) {
            const int id = t + u * 256, r = id >> 3, ch = (id & 7) * 8;
            cp16(smem_u32(smem + r * ASTR + ch), qsrc + (size_t)r * 64 + ch);
        }
        cp_commit(); cp_wait0(); __syncthreads();
        #pragma unroll
        for (int kk = 0; kk < 4; kk++) ldsm_x4(ql[kk], qAddr + kk * 32);
        __syncthreads();
    }

    float s[8][4], o[8][4];
    float m0 = -1e30f, m1 = -1e30f, l0 = 0.f, l1 = 0.f;
    #pragma unroll
    for (int f = 0; f < 8; f++)
        #pragma unroll
        for (int q = 0; q < 4; q++) o[f][q] = 0.f;

    const int r_row0 = q0 + rw + (lane >> 2);
    const int xq0 = r_row0 >> 5,       yq0 = r_row0 & 31;
    const int xq1 = (r_row0 + 8) >> 5, yq1 = (r_row0 + 8) & 31;

#define LOAD_TILE(kt, bf) do {                                                   \
    _Pragma("unroll")                                                            \
    for (int u = 0; u < 8; u++) {                                                \
        const int p = u >> 1;                                                    \
        const int id = t + u * 256;                                              \
        const int rr = (id >> 3) & 63, ch = (id & 7) * 8;                        \
        const __nv_bfloat16* src = (p == 0) ? g_kh : (p == 1) ? g_kl             \
                                 : (p == 2) ? g_vh : g_vl;                       \
        cp16(smem_u32(smem + (((bf) * 4 + p) * 64 + rr) * ASTR + ch),            \
             src + ((size_t)bh * NTOK + (kt) * 64 + rr) * 64 + ch);              \
    }                                                                            \
    cp_commit(); } while (0)

    LOAD_TILE(0, 0);

    for (int kt = 0; kt < 16; kt++) {
        const int buf = kt & 1;
        if (kt < 15) { LOAD_TILE(kt + 1, 1 - buf); cp_wait1(); }
        else         { cp_wait0(); }
        __syncthreads();

        const uint32_t base = smem_u32(smem) + buf * 4 * PLANE_B;
        const uint32_t laddr = ((lane & 15) * ASTR + ((lane >> 4) << 3)) * 2;

        // ---- S = Q K^T (3-limb) ----
        #pragma unroll
        for (int f = 0; f < 8; f++)
            #pragma unroll
            for (int q = 0; q < 4; q++) s[f][q] = 0.f;

        #pragma unroll
        for (int kk = 0; kk < 4; kk++) {
            #pragma unroll
            for (int ng = 0; ng < 4; ng++) {
                uint32_t kh[4], kl[4];
                const uint32_t ad = base + laddr + (ng * 16 * ASTR + kk * 16) * 2;
                ldsm_x4(kh, ad);
                ldsm_x4(kl, ad + PLANE_B);
                uint32_t bh0[2] = {kh[0], kh[2]}, bh1[2] = {kh[1], kh[3]};
                uint32_t bl0[2] = {kl[0], kl[2]}, bl1[2] = {kl[1], kl[3]};
                mma_bf16(s[2*ng],   qh[kk], bh0);
                mma_bf16(s[2*ng],   qh[kk], bl0);
                mma_bf16(s[2*ng],   ql[kk], bh0);
                mma_bf16(s[2*ng+1], qh[kk], bh1);
                mma_bf16(s[2*ng+1], qh[kk], bl1);
                mma_bf16(s[2*ng+1], ql[kk], bh1);
            }
        }

        // ---- bias + online softmax ----
        float tm0 = -1e30f, tm1 = -1e30f;
        const int cb = kt * 64 + (lane & 3) * 2;
        #pragma unroll
        for (int f = 0; f < 8; f++) {
            const int c0 = cb + f * 8, c1 = c0 + 1;
            const int cx0 = c0 >> 5, cy0 = c0 & 31;
            const int cx1 = c1 >> 5, cy1 = c1 & 31;
            s[f][0] += s_bias[abs(xq0 - cx0) * 32 + abs(yq0 - cy0)];
            s[f][1] += s_bias[abs(xq0 - cx1) * 32 + abs(yq0 - cy1)];
            s[f][2] += s_bias[abs(xq1 - cx0) * 32 + abs(yq1 - cy0)];
            s[f][3] += s_bias[abs(xq1 - cx1) * 32 + abs(yq1 - cy1)];
            tm0 = fmaxf(tm0, fmaxf(s[f][0], s[f][1]));
            tm1 = fmaxf(tm1, fmaxf(s[f][2], s[f][3]));
        }
        tm0 = fmaxf(tm0, __shfl_xor_sync(0xffffffffu, tm0, 1));
        tm0 = fmaxf(tm0, __shfl_xor_sync(0xffffffffu, tm0, 2));
        tm1 = fmaxf(tm1, __shfl_xor_sync(0xffffffffu, tm1, 1));
        tm1 = fmaxf(tm1, __shfl_xor_sync(0xffffffffu, tm1, 2));

        const float mn0 = fmaxf(m0, tm0), mn1 = fmaxf(m1, tm1);
        const float fac0 = __expf(m0 - mn0), fac1 = __expf(m1 - mn1);
        m0 = mn0; m1 = mn1;
        l0 *= fac0; l1 *= fac1;
        #pragma unroll
        for (int f = 0; f < 8; f++) {
            s[f][0] = __expf(s[f][0] - m0); s[f][1] = __expf(s[f][1] - m0);
            s[f][2] = __expf(s[f][2] - m1); s[f][3] = __expf(s[f][3] - m1);
            l0 += s[f][0] + s[f][1];
            l1 += s[f][2] + s[f][3];
            o[f][0] *= fac0; o[f][1] *= fac0; o[f][2] *= fac1; o[f][3] *= fac1;
        }

        // ---- O += P V (3-limb), P frags built in-register from S frags ----
        const uint32_t vbase = base + 2 * PLANE_B;
        #pragma unroll
        for (int kk2 = 0; kk2 < 4; kk2++) {
            uint32_t ah[4], al[4];
            split2(s[2*kk2][0],   s[2*kk2][1],   ah[0], al[0]);
            split2(s[2*kk2][2],   s[2*kk2][3],   ah[1], al[1]);
            split2(s[2*kk2+1][0], s[2*kk2+1][1], ah[2], al[2]);
            split2(s[2*kk2+1][2], s[2*kk2+1][3], ah[3], al[3]);
            #pragma unroll
            for (int dg = 0; dg < 4; dg++) {
                const int nf = dg * 2;
                uint32_t vh[4], vl[4];
                const uint32_t ad = vbase + laddr + (kk2 * 16 * ASTR + dg * 16) * 2;
                ldsm_x4_t(vh, ad);
                ldsm_x4_t(vl, ad + PLANE_B);
                uint32_t bh0[2] = {vh[0], vh[1]}, bh1[2] = {vh[2], vh[3]};
                uint32_t bl0[2] = {vl[0], vl[1]}, bl1[2] = {vl[2], vl[3]};
                mma_bf16(o[nf],   ah, bh0);
                mma_bf16(o[nf],   ah, bl0);
                mma_bf16(o[nf],   al, bh0);
                mma_bf16(o[nf+1], ah, bh1);
                mma_bf16(o[nf+1], ah, bl1);
                mma_bf16(o[nf+1], al, bh1);
            }
        }
        __syncthreads();
    }

    // ---- epilogue: normalize, write attention-output limbs ----
    l0 += __shfl_xor_sync(0xffffffffu, l0, 1);
    l0 += __shfl_xor_sync(0xffffffffu, l0, 2);
    l1 += __shfl_xor_sync(0xffffffffu, l1, 1);
    l1 += __shfl_xor_sync(0xffffffffu, l1, 2);
    const float inv0 = 1.0f / l0, inv1 = 1.0f / l1;

    const size_t rbase0 = ((size_t)(b * NTOK + r_row0)) * EMB + h * 64;
    const size_t rbase1 = rbase0 + (size_t)8 * EMB;
    #pragma unroll
    for (int f = 0; f < 8; f++) {
        const int d = f * 8 + (lane & 3) * 2;
        uint32_t hi, lo;
        split2(o[f][0] * inv0, o[f][1] * inv0, hi, lo);
        *(uint32_t*)&g_aoh[rbase0 + d] = hi;
        *(uint32_t*)&g_aol[rbase0 + d] = lo;
        split2(o[f][2] * inv1, o[f][3] * inv1, hi, lo);
        *(uint32_t*)&g_aoh[rbase1 + d] = hi;
        *(uint32_t*)&g_aol[rbase1 + d] = lo;
    }
}

// ============================================================================
extern "C" void kernel_launch(void* const* d_in, const int* in_sizes, int n_in,
                              void* d_out, int out_size)
{
    const float* x     = (const float*)d_in[0];
    const float* Wqkv  = (const float*)d_in[1];
    const float* ab    = (const float*)d_in[2];
    // d_in[3] = bias_idxs : not needed (idx = |dx|*32 + |dy| analytically)
    const float* Wout  = (const float*)d_in[4];
    const float* bout  = (const float*)d_in[5];
    float* out = (float*)d_out;

    cudaFuncSetAttribute(attn_mma, cudaFuncAttributeMaxDynamicSharedMemorySize,
                         ATTN_SMEM);

    convert_kernel<<<8192*1024/1024, 256>>>(x,    0, 8192*1024);
    convert_kernel<<<3072*1024/1024, 256>>>(Wqkv, 1, 3072*1024);
    convert_kernel<<<1024*1024/1024, 256>>>(Wout, 2, 1024*1024);

    mma_gemm<0><<<dim3(3072/128, 8192/128), 512>>>(nullptr, nullptr);
    attn_mma<<<dim3(NTOK/128, HEADS, BATCH), 256, ATTN_SMEM>>>(ab);
    mma_gemm<1><<<dim3(1024/128, 8192/128), 512>>>(bout, out);
}

// round 6
// speedup vs baseline: 2.5552x; 1.0062x over previous
#include <cuda_runtime.h>
#include <cuda_bf16.h>
#include <cstdint>

#define BATCH 8
#define HEADS 16
#define NTOK  1024
#define DHEAD 64
#define EMB   1024
#define KD    1024

// ---- scratch (allocation-free rule: __device__ globals) ----
__device__ __nv_bfloat16 g_qh[BATCH*HEADS*NTOK*DHEAD];
__device__ __nv_bfloat16 g_ql[BATCH*HEADS*NTOK*DHEAD];
__device__ __nv_bfloat16 g_kh[BATCH*HEADS*NTOK*DHEAD];
__device__ __nv_bfloat16 g_kl[BATCH*HEADS*NTOK*DHEAD];
__device__ __nv_bfloat16 g_vh[BATCH*HEADS*NTOK*DHEAD];
__device__ __nv_bfloat16 g_vl[BATCH*HEADS*NTOK*DHEAD];

__device__ __nv_bfloat16 g_xh [8192*1024];
__device__ __nv_bfloat16 g_xl [8192*1024];
__device__ __nv_bfloat16 g_wqh[3072*1024];
__device__ __nv_bfloat16 g_wql[3072*1024];
__device__ __nv_bfloat16 g_woh[1024*1024];
__device__ __nv_bfloat16 g_wol[1024*1024];
__device__ __nv_bfloat16 g_aoh[8192*1024];
__device__ __nv_bfloat16 g_aol[8192*1024];

// ---------------------------------------------------------------------------
__device__ __forceinline__ uint32_t smem_u32(const void* p) {
    return (uint32_t)__cvta_generic_to_shared(p);
}
__device__ __forceinline__ uint32_t pack_bf2(float x, float y) {
    __nv_bfloat162 t = __floats2bfloat162_rn(x, y);
    return *reinterpret_cast<uint32_t*>(&t);
}
__device__ __forceinline__ void split2(float x, float y, uint32_t& hi, uint32_t& lo) {
    float hx = __bfloat162float(__float2bfloat16(x));
    float hy = __bfloat162float(__float2bfloat16(y));
    hi = pack_bf2(x, y);
    lo = pack_bf2(x - hx, y - hy);
}
__device__ __forceinline__ void ldsm_x4(uint32_t* r, uint32_t addr) {
    asm volatile("ldmatrix.sync.aligned.m8n8.x4.shared.b16 {%0,%1,%2,%3},[%4];"
                 : "=r"(r[0]), "=r"(r[1]), "=r"(r[2]), "=r"(r[3]) : "r"(addr));
}
__device__ __forceinline__ void ldsm_x4_t(uint32_t* r, uint32_t addr) {
    asm volatile("ldmatrix.sync.aligned.m8n8.x4.trans.shared.b16 {%0,%1,%2,%3},[%4];"
                 : "=r"(r[0]), "=r"(r[1]), "=r"(r[2]), "=r"(r[3]) : "r"(addr));
}
__device__ __forceinline__ void mma_bf16(float* c, const uint32_t* a, const uint32_t* b) {
    asm volatile("mma.sync.aligned.m16n8k16.row.col.f32.bf16.bf16.f32 "
                 "{%0,%1,%2,%3},{%4,%5,%6,%7},{%8,%9},{%0,%1,%2,%3};"
                 : "+f"(c[0]), "+f"(c[1]), "+f"(c[2]), "+f"(c[3])
                 : "r"(a[0]), "r"(a[1]), "r"(a[2]), "r"(a[3]), "r"(b[0]), "r"(b[1]));
}
__device__ __forceinline__ void cp16(uint32_t dst, const void* src) {
    asm volatile("cp.async.ca.shared.global [%0],[%1],16;" :: "r"(dst), "l"(src));
}
__device__ __forceinline__ void cp_commit() { asm volatile("cp.async.commit_group;"); }
__device__ __forceinline__ void cp_wait0() { asm volatile("cp.async.wait_group 0;"); }
__device__ __forceinline__ void cp_wait1() { asm volatile("cp.async.wait_group 1;"); }

// ---------------------------------------------------------------------------
// fp32 -> (hi, lo) bf16 limb conversion.  which: 0=x, 1=Wqkv, 2=Wout
// ---------------------------------------------------------------------------
__global__ __launch_bounds__(256) void convert_kernel(const float* __restrict__ src,
                                                      int which, int n)
{
    int i = (blockIdx.x * 256 + threadIdx.x) * 4;
    if (i >= n) return;
    __nv_bfloat16 *hi, *lo;
    if (which == 0)      { hi = g_xh;  lo = g_xl;  }
    else if (which == 1) { hi = g_wqh; lo = g_wql; }
    else                 { hi = g_woh; lo = g_wol; }

    float4 v = *(const float4*)(src + i);
    uint2 ph, pl;
    split2(v.x, v.y, ph.x, pl.x);
    split2(v.z, v.w, ph.y, pl.y);
    *(uint2*)&hi[i] = ph;
    *(uint2*)&pl;   // no-op silencer
    *(uint2*)&lo[i] = pl;
}

// ---------------------------------------------------------------------------
// Split-bf16 HMMA GEMM: C[m,c] = sum_k A(m,k)*B(c,k) = AhBh + AhBl + AlBh
// Block 128x128, 256 thr (8 warps as 2M x 4N), warp tile 64x32, K-step 32,
// cp.async double-buffered, 2 CTAs/SM.
// MODE 0: A=x limbs, B=Wqkv limbs -> limb planes g_q*/g_k*/g_v* (q *= 0.125)
// MODE 1: A=attn-out limbs, B=Wout limbs -> +bias -> C (fp32)
// ---------------------------------------------------------------------------
#define GSTR 40                           // smem row stride (elems), conflict-free
#define PL   (128 * GSTR)                 // plane elems (Ah/Al/Bh/Bl)
#define GBUF (4 * PL)                     // buffer elems
#define G_SMEM_B (2 * GBUF * 2)           // bytes: 81920

template<int MODE>
__global__ __launch_bounds__(256, 2) void mma_gemm(const float* __restrict__ bias,
                                                   float* __restrict__ C)
{
    extern __shared__ __nv_bfloat16 gs[];

    const int t    = threadIdx.x;
    const int lane = t & 31;
    const int wid  = t >> 5;
    const int wm   = (wid & 1) << 6;       // 0 / 64
    const int wn   = (wid >> 1) << 5;      // 0..96
    const int m0   = blockIdx.y * 128;
    const int n0   = blockIdx.x * 128;

    const __nv_bfloat16* Ah = (MODE == 0) ? g_xh  : g_aoh;
    const __nv_bfloat16* Al = (MODE == 0) ? g_xl  : g_aol;
    const __nv_bfloat16* Bh = (MODE == 0) ? g_wqh : g_woh;
    const __nv_bfloat16* Bl = (MODE == 0) ? g_wql : g_wol;

    // cp.async mapping: 128 rows x 4 chunks(8 elems) per plane; 2 per thread/plane
    const int r1 = t >> 1;                 // u=0 rows 0..127
    const int c1 = (t & 1) << 3;           // chunk col 0/8
    const int c2 = c1 + 16;                // chunk col 16/24
    const uint32_t s_base = smem_u32(gs);

#define G_LOAD(st, bf) do {                                                       \
    const int k0 = (st) * 32;                                                     \
    const uint32_t bo = s_base + (uint32_t)(bf) * (GBUF * 2);                     \
    const size_t ga = (size_t)(m0 + r1) * KD + k0;                                \
    const size_t gb = (size_t)(n0 + r1) * KD + k0;                                \
    const uint32_t so1 = (uint32_t)(r1 * GSTR + c1) * 2;                          \
    const uint32_t so2 = (uint32_t)(r1 * GSTR + c2) * 2;                          \
    cp16(bo + so1,               Ah + ga + c1);                                   \
    cp16(bo + so2,               Ah + ga + c2);                                   \
    cp16(bo + PL * 2 + so1,      Al + ga + c1);                                   \
    cp16(bo + PL * 2 + so2,      Al + ga + c2);                                   \
    cp16(bo + PL * 4 + so1,      Bh + gb + c1);                                   \
    cp16(bo + PL * 4 + so2,      Bh + gb + c2);                                   \
    cp16(bo + PL * 6 + so1,      Bl + gb + c1);                                   \
    cp16(bo + PL * 6 + so2,      Bl + gb + c2);                                   \
    cp_commit(); } while (0)

    // ldmatrix lane addressing
    const int a_r = wm + (lane & 15);
    const int a_c = (lane >> 4) << 3;
    const int b_r = wn + ((lane >> 4) << 3) + (lane & 7);
    const int b_c = ((lane >> 3) & 1) << 3;

    float acc[4][4][4];
    #pragma unroll
    for (int mt = 0; mt < 4; mt++)
        #pragma unroll
        for (int nt = 0; nt < 4; nt++)
            #pragma unroll
            for (int q = 0; q < 4; q++) acc[mt][nt][q] = 0.f;

    G_LOAD(0, 0);

    const int NSTEP = KD / 32;             // 32
    for (int st = 0; st < NSTEP; st++) {
        const int buf = st & 1;
        if (st + 1 < NSTEP) { G_LOAD(st + 1, 1 - buf); cp_wait1(); }
        else                { cp_wait0(); }
        __syncthreads();

        const uint32_t bo = s_base + (uint32_t)buf * (GBUF * 2);
        #pragma unroll
        for (int kk = 0; kk < 32; kk += 16) {
            uint32_t ah[4][4], al[4][4], bhf[2][4], blf[2][4];
            #pragma unroll
            for (int mt = 0; mt < 4; mt++) {
                const uint32_t ad = bo + (uint32_t)(((a_r + mt * 16) * GSTR) + kk + a_c) * 2;
                ldsm_x4(ah[mt], ad);
                ldsm_x4(al[mt], ad + PL * 2);
            }
            #pragma unroll
            for (int pr = 0; pr < 2; pr++) {
                const uint32_t bd = bo + (uint32_t)(((b_r + pr * 16) * GSTR) + kk + b_c) * 2 + PL * 4;
                ldsm_x4(bhf[pr], bd);
                ldsm_x4(blf[pr], bd + PL * 2);
            }
            #pragma unroll
            for (int mt = 0; mt < 4; mt++)
                #pragma unroll
                for (int nt = 0; nt < 4; nt++) {
                    uint32_t* B0 = &bhf[nt >> 1][(nt & 1) * 2];
                    uint32_t* B1 = &blf[nt >> 1][(nt & 1) * 2];
                    mma_bf16(acc[mt][nt], ah[mt], B0);
                    mma_bf16(acc[mt][nt], ah[mt], B1);
                    mma_bf16(acc[mt][nt], al[mt], B0);
                }
        }
        __syncthreads();
    }

    // ---- epilogue ----
    const int part = (MODE == 0) ? (n0 >> 10) : 0;
    const int e0   = n0 & 1023;
    #pragma unroll
    for (int mt = 0; mt < 4; mt++) {
        #pragma unroll
        for (int half = 0; half < 2; half++) {
            const int m = m0 + wm + mt * 16 + (lane >> 2) + half * 8;
            if (MODE == 0) {
                const int bb = m >> 10, nn = m & 1023;
                #pragma unroll
                for (int nt = 0; nt < 4; nt++) {
                    const int e  = e0 + wn + nt * 8 + (lane & 3) * 2;
                    const int hh = e >> 6, d = e & 63;
                    const size_t off = ((size_t)((bb * HEADS + hh) * NTOK + nn) << 6) + d;
                    float vx = acc[mt][nt][half * 2], vy = acc[mt][nt][half * 2 + 1];
                    uint32_t hi, lo;
                    if (part == 0) {
                        vx *= 0.125f; vy *= 0.125f;
                        split2(vx, vy, hi, lo);
                        *(uint32_t*)&g_qh[off] = hi; *(uint32_t*)&g_ql[off] = lo;
                    } else if (part == 1) {
                        split2(vx, vy, hi, lo);
                        *(uint32_t*)&g_kh[off] = hi; *(uint32_t*)&g_kl[off] = lo;
                    } else {
                        split2(vx, vy, hi, lo);
                        *(uint32_t*)&g_vh[off] = hi; *(uint32_t*)&g_vl[off] = lo;
                    }
                }
            } else {
                #pragma unroll
                for (int nt = 0; nt < 4; nt++) {
                    const int cg = n0 + wn + nt * 8 + (lane & 3) * 2;
                    const float2 b2 = *(const float2*)&bias[cg];
                    float2 v = make_float2(acc[mt][nt][half * 2] + b2.x,
                                           acc[mt][nt][half * 2 + 1] + b2.y);
                    *(float2*)&C[(size_t)m * EMB + cg] = v;
                }
            }
        }
    }
}

// ============================================================================
// Tensor-core flash attention, split-bf16 limbs everywhere. (R3, unchanged)
// ============================================================================
#define ASTR 72
#define PLANE_B (64 * ASTR * 2)
#define ATTN_SMEM (2 * 4 * 64 * ASTR * 2 + 1024 * 4)

__global__ __launch_bounds__(256) void attn_mma(const float* __restrict__ biases)
{
    extern __shared__ __nv_bfloat16 smem[];
    float* s_bias = (float*)(smem + 2 * 4 * 64 * ASTR);

    const int t = threadIdx.x, lane = t & 31, w = t >> 5;
    const int qt = blockIdx.x, h = blockIdx.y, b = blockIdx.z;
    const int bh = b * HEADS + h;
    const int q0 = qt * 128;
    const int rw = w * 16;

    for (int i = t; i < 1024; i += 256) s_bias[i] = biases[h * 1024 + i];

    uint32_t qh[4][4], ql[4][4];
    const uint32_t qAddr = smem_u32(smem) + ((rw + (lane & 15)) * ASTR + ((lane >> 4) << 3)) * 2;
    {
        const __nv_bfloat16* qsrc = g_qh + ((size_t)bh * NTOK + q0) * 64;
        #pragma unroll
        for (int u = 0; u < 4; u++) {
            const int id = t + u * 256, r = id >> 3, ch = (id & 7) * 8;
            cp16(smem_u32(smem + r * ASTR + ch), qsrc + (size_t)r * 64 + ch);
        }
        cp_commit(); cp_wait0(); __syncthreads();
        #pragma unroll
        for (int kk = 0; kk < 4; kk++) ldsm_x4(qh[kk], qAddr + kk * 32);
        __syncthreads();

        qsrc = g_ql + ((size_t)bh * NTOK + q0) * 64;
        #pragma unroll
        for (int u = 0; u < 4; u++) {
            const int id = t + u * 256, r = id >> 3, ch = (id & 7) * 8;
            cp16(smem_u32(smem + r * ASTR + ch), qsrc + (size_t)r * 64 + ch);
        }
        cp_commit(); cp_wait0(); __syncthreads();
        #pragma unroll
        for (int kk = 0; kk < 4; kk++) ldsm_x4(ql[kk], qAddr + kk * 32);
        __syncthreads();
    }

    float s[8][4], o[8][4];
    float m0 = -1e30f, m1 = -1e30f, l0 = 0.f, l1 = 0.f;
    #pragma unroll
    for (int f = 0; f < 8; f++)
        #pragma unroll
        for (int q = 0; q < 4; q++) o[f][q] = 0.f;

    const int r_row0 = q0 + rw + (lane >> 2);
    const int xq0 = r_row0 >> 5,       yq0 = r_row0 & 31;
    const int xq1 = (r_row0 + 8) >> 5, yq1 = (r_row0 + 8) & 31;

#define LOAD_TILE(kt, bf) do {                                                   \
    _Pragma("unroll")                                                            \
    for (int u = 0; u < 8; u++) {                                                \
        const int p = u >> 1;                                                    \
        const int id = t + u * 256;                                              \
        const int rr = (id >> 3) & 63, ch = (id & 7) * 8;                        \
        const __nv_bfloat16* src = (p == 0) ? g_kh : (p == 1) ? g_kl             \
                                 : (p == 2) ? g_vh : g_vl;                       \
        cp16(smem_u32(smem + (((bf) * 4 + p) * 64 + rr) * ASTR + ch),            \
             src + ((size_t)bh * NTOK + (kt) * 64 + rr) * 64 + ch);              \
    }                                                                            \
    cp_commit(); } while (0)

    LOAD_TILE(0, 0);

    for (int kt = 0; kt < 16; kt++) {
        const int buf = kt & 1;
        if (kt < 15) { LOAD_TILE(kt + 1, 1 - buf); cp_wait1(); }
        else         { cp_wait0(); }
        __syncthreads();

        const uint32_t base = smem_u32(smem) + buf * 4 * PLANE_B;
        const uint32_t laddr = ((lane & 15) * ASTR + ((lane >> 4) << 3)) * 2;

        #pragma unroll
        for (int f = 0; f < 8; f++)
            #pragma unroll
            for (int q = 0; q < 4; q++) s[f][q] = 0.f;

        #pragma unroll
        for (int kk = 0; kk < 4; kk++) {
            #pragma unroll
            for (int ng = 0; ng < 4; ng++) {
                uint32_t kh[4], kl[4];
                const uint32_t ad = base + laddr + (ng * 16 * ASTR + kk * 16) * 2;
                ldsm_x4(kh, ad);
                ldsm_x4(kl, ad + PLANE_B);
                uint32_t bh0[2] = {kh[0], kh[2]}, bh1[2] = {kh[1], kh[3]};
                uint32_t bl0[2] = {kl[0], kl[2]}, bl1[2] = {kl[1], kl[3]};
                mma_bf16(s[2*ng],   qh[kk], bh0);
                mma_bf16(s[2*ng],   qh[kk], bl0);
                mma_bf16(s[2*ng],   ql[kk], bh0);
                mma_bf16(s[2*ng+1], qh[kk], bh1);
                mma_bf16(s[2*ng+1], qh[kk], bl1);
                mma_bf16(s[2*ng+1], ql[kk], bh1);
            }
        }

        float tm0 = -1e30f, tm1 = -1e30f;
        const int cb = kt * 64 + (lane & 3) * 2;
        #pragma unroll
        for (int f = 0; f < 8; f++) {
            const int c0 = cb + f * 8, c1 = c0 + 1;
            const int cx0 = c0 >> 5, cy0 = c0 & 31;
            const int cx1 = c1 >> 5, cy1 = c1 & 31;
            s[f][0] += s_bias[abs(xq0 - cx0) * 32 + abs(yq0 - cy0)];
            s[f][1] += s_bias[abs(xq0 - cx1) * 32 + abs(yq0 - cy1)];
            s[f][2] += s_bias[abs(xq1 - cx0) * 32 + abs(yq1 - cy0)];
            s[f][3] += s_bias[abs(xq1 - cx1) * 32 + abs(yq1 - cy1)];
            tm0 = fmaxf(tm0, fmaxf(s[f][0], s[f][1]));
            tm1 = fmaxf(tm1, fmaxf(s[f][2], s[f][3]));
        }
        tm0 = fmaxf(tm0, __shfl_xor_sync(0xffffffffu, tm0, 1));
        tm0 = fmaxf(tm0, __shfl_xor_sync(0xffffffffu, tm0, 2));
        tm1 = fmaxf(tm1, __shfl_xor_sync(0xffffffffu, tm1, 1));
        tm1 = fmaxf(tm1, __shfl_xor_sync(0xffffffffu, tm1, 2));

        const float mn0 = fmaxf(m0, tm0), mn1 = fmaxf(m1, tm1);
        const float fac0 = __expf(m0 - mn0), fac1 = __expf(m1 - mn1);
        m0 = mn0; m1 = mn1;
        l0 *= fac0; l1 *= fac1;
        #pragma unroll
        for (int f = 0; f < 8; f++) {
            s[f][0] = __expf(s[f][0] - m0); s[f][1] = __expf(s[f][1] - m0);
            s[f][2] = __expf(s[f][2] - m1); s[f][3] = __expf(s[f][3] - m1);
            l0 += s[f][0] + s[f][1];
            l1 += s[f][2] + s[f][3];
            o[f][0] *= fac0; o[f][1] *= fac0; o[f][2] *= fac1; o[f][3] *= fac1;
        }

        const uint32_t vbase = base + 2 * PLANE_B;
        #pragma unroll
        for (int kk2 = 0; kk2 < 4; kk2++) {
            uint32_t ah[4], al[4];
            split2(s[2*kk2][0],   s[2*kk2][1],   ah[0], al[0]);
            split2(s[2*kk2][2],   s[2*kk2][3],   ah[1], al[1]);
            split2(s[2*kk2+1][0], s[2*kk2+1][1], ah[2], al[2]);
            split2(s[2*kk2+1][2], s[2*kk2+1][3], ah[3], al[3]);
            #pragma unroll
            for (int dg = 0; dg < 4; dg++) {
                const int nf = dg * 2;
                uint32_t vh[4], vl[4];
                const uint32_t ad = vbase + laddr + (kk2 * 16 * ASTR + dg * 16) * 2;
                ldsm_x4_t(vh, ad);
                ldsm_x4_t(vl, ad + PLANE_B);
                uint32_t bh0[2] = {vh[0], vh[1]}, bh1[2] = {vh[2], vh[3]};
                uint32_t bl0[2] = {vl[0], vl[1]}, bl1[2] = {vl[2], vl[3]};
                mma_bf16(o[nf],   ah, bh0);
                mma_bf16(o[nf],   ah, bl0);
                mma_bf16(o[nf],   al, bh0);
                mma_bf16(o[nf+1], ah, bh1);
                mma_bf16(o[nf+1], ah, bl1);
                mma_bf16(o[nf+1], al, bh1);
            }
        }
        __syncthreads();
    }

    l0 += __shfl_xor_sync(0xffffffffu, l0, 1);
    l0 += __shfl_xor_sync(0xffffffffu, l0, 2);
    l1 += __shfl_xor_sync(0xffffffffu, l1, 1);
    l1 += __shfl_xor_sync(0xffffffffu, l1, 2);
    const float inv0 = 1.0f / l0, inv1 = 1.0f / l1;

    const size_t rbase0 = ((size_t)(b * NTOK + r_row0)) * EMB + h * 64;
    const size_t rbase1 = rbase0 + (size_t)8 * EMB;
    #pragma unroll
    for (int f = 0; f < 8; f++) {
        const int d = f * 8 + (lane & 3) * 2;
        uint32_t hi, lo;
        split2(o[f][0] * inv0, o[f][1] * inv0, hi, lo);
        *(uint32_t*)&g_aoh[rbase0 + d] = hi;
        *(uint32_t*)&g_aol[rbase0 + d] = lo;
        split2(o[f][2] * inv1, o[f][3] * inv1, hi, lo);
        *(uint32_t*)&g_aoh[rbase1 + d] = hi;
        *(uint32_t*)&g_aol[rbase1 + d] = lo;
    }
}

// ============================================================================
extern "C" void kernel_launch(void* const* d_in, const int* in_sizes, int n_in,
                              void* d_out, int out_size)
{
    const float* x     = (const float*)d_in[0];
    const float* Wqkv  = (const float*)d_in[1];
    const float* ab    = (const float*)d_in[2];
    // d_in[3] = bias_idxs : not needed (idx = |dx|*32 + |dy| analytically)
    const float* Wout  = (const float*)d_in[4];
    const float* bout  = (const float*)d_in[5];
    float* out = (float*)d_out;

    cudaFuncSetAttribute(attn_mma, cudaFuncAttributeMaxDynamicSharedMemorySize,
                         ATTN_SMEM);
    cudaFuncSetAttribute(mma_gemm<0>, cudaFuncAttributeMaxDynamicSharedMemorySize,
                         G_SMEM_B);
    cudaFuncSetAttribute(mma_gemm<1>, cudaFuncAttributeMaxDynamicSharedMemorySize,
                         G_SMEM_B);

    convert_kernel<<<8192*1024/1024, 256>>>(x,    0, 8192*1024);
    convert_kernel<<<3072*1024/1024, 256>>>(Wqkv, 1, 3072*1024);
    convert_kernel<<<1024*1024/1024, 256>>>(Wout, 2, 1024*1024);

    mma_gemm<0><<<dim3(3072/128, 8192/128), 256, G_SMEM_B>>>(nullptr, nullptr);
    attn_mma<<<dim3(NTOK/128, HEADS, BATCH), 256, ATTN_SMEM>>>(ab);
    mma_gemm<1><<<dim3(1024/128, 8192/128), 256, G_SMEM_B>>>(bout, out);
}

// round 7
// speedup vs baseline: 2.6130x; 1.0226x over previous
#include <cuda_runtime.h>
#include <cuda_bf16.h>
#include <cstdint>

#define BATCH 8
#define HEADS 16
#define NTOK  1024
#define DHEAD 64
#define EMB   1024
#define KD    1024

// ---- scratch (allocation-free rule: __device__ globals) ----
__device__ __nv_bfloat16 g_qh[BATCH*HEADS*NTOK*DHEAD];
__device__ __nv_bfloat16 g_ql[BATCH*HEADS*NTOK*DHEAD];
__device__ __nv_bfloat16 g_kh[BATCH*HEADS*NTOK*DHEAD];
__device__ __nv_bfloat16 g_kl[BATCH*HEADS*NTOK*DHEAD];
__device__ __nv_bfloat16 g_vh[BATCH*HEADS*NTOK*DHEAD];
__device__ __nv_bfloat16 g_vl[BATCH*HEADS*NTOK*DHEAD];

__device__ __nv_bfloat16 g_xh [8192*1024];
__device__ __nv_bfloat16 g_xl [8192*1024];
__device__ __nv_bfloat16 g_wqh[3072*1024];
__device__ __nv_bfloat16 g_wql[3072*1024];
__device__ __nv_bfloat16 g_woh[1024*1024];
__device__ __nv_bfloat16 g_wol[1024*1024];
__device__ __nv_bfloat16 g_aoh[8192*1024];
__device__ __nv_bfloat16 g_aol[8192*1024];

// ---------------------------------------------------------------------------
__device__ __forceinline__ uint32_t smem_u32(const void* p) {
    return (uint32_t)__cvta_generic_to_shared(p);
}
__device__ __forceinline__ uint32_t pack_bf2(float x, float y) {
    __nv_bfloat162 t = __floats2bfloat162_rn(x, y);
    return *reinterpret_cast<uint32_t*>(&t);
}
__device__ __forceinline__ void split2(float x, float y, uint32_t& hi, uint32_t& lo) {
    float hx = __bfloat162float(__float2bfloat16(x));
    float hy = __bfloat162float(__float2bfloat16(y));
    hi = pack_bf2(x, y);
    lo = pack_bf2(x - hx, y - hy);
}
__device__ __forceinline__ void ldsm_x4(uint32_t* r, uint32_t addr) {
    asm volatile("ldmatrix.sync.aligned.m8n8.x4.shared.b16 {%0,%1,%2,%3},[%4];"
                 : "=r"(r[0]), "=r"(r[1]), "=r"(r[2]), "=r"(r[3]) : "r"(addr));
}
__device__ __forceinline__ void ldsm_x4_t(uint32_t* r, uint32_t addr) {
    asm volatile("ldmatrix.sync.aligned.m8n8.x4.trans.shared.b16 {%0,%1,%2,%3},[%4];"
                 : "=r"(r[0]), "=r"(r[1]), "=r"(r[2]), "=r"(r[3]) : "r"(addr));
}
__device__ __forceinline__ void mma_bf16(float* c, const uint32_t* a, const uint32_t* b) {
    asm volatile("mma.sync.aligned.m16n8k16.row.col.f32.bf16.bf16.f32 "
                 "{%0,%1,%2,%3},{%4,%5,%6,%7},{%8,%9},{%0,%1,%2,%3};"
                 : "+f"(c[0]), "+f"(c[1]), "+f"(c[2]), "+f"(c[3])
                 : "r"(a[0]), "r"(a[1]), "r"(a[2]), "r"(a[3]), "r"(b[0]), "r"(b[1]));
}
__device__ __forceinline__ void cp16(uint32_t dst, const void* src) {
    asm volatile("cp.async.ca.shared.global [%0],[%1],16;" :: "r"(dst), "l"(src));
}
__device__ __forceinline__ void cp_commit() { asm volatile("cp.async.commit_group;"); }
__device__ __forceinline__ void cp_wait0() { asm volatile("cp.async.wait_group 0;"); }
__device__ __forceinline__ void cp_wait1() { asm volatile("cp.async.wait_group 1;"); }

// ---------------------------------------------------------------------------
// fp32 -> (hi, lo) bf16 limb conversion.  which: 0=x, 1=Wqkv, 2=Wout
// ---------------------------------------------------------------------------
__global__ __launch_bounds__(256) void convert_kernel(const float* __restrict__ src,
                                                      int which, int n)
{
    int i = (blockIdx.x * 256 + threadIdx.x) * 4;
    if (i >= n) return;
    __nv_bfloat16 *hi, *lo;
    if (which == 0)      { hi = g_xh;  lo = g_xl;  }
    else if (which == 1) { hi = g_wqh; lo = g_wql; }
    else                 { hi = g_woh; lo = g_wol; }

    float4 v = *(const float4*)(src + i);
    uint2 ph, pl;
    split2(v.x, v.y, ph.x, pl.x);
    split2(v.z, v.w, ph.y, pl.y);
    *(uint2*)&hi[i] = ph;
    *(uint2*)&lo[i] = pl;
}

// ---------------------------------------------------------------------------
// Split-bf16 HMMA GEMM: C[m,c] = sum_k A(m,k)*B(c,k) = AhBh + AhBl + AlBh
// Block 128x256, 256 thr (8 warps as 2M x 4N), warp tile 64x64, K-step 32,
// cp.async double-buffered, 1 CTA/SM (123KB smem).
// MODE 0: A=x limbs, B=Wqkv limbs -> limb planes g_q*/g_k*/g_v* (q *= 0.125)
// MODE 1: A=attn-out limbs, B=Wout limbs -> +bias -> C (fp32)
// ---------------------------------------------------------------------------
#define GSTR 40                           // smem row stride (elems), conflict-free
#define APL  (128 * GSTR)                 // A limb plane elems (5120)
#define BPL  (256 * GSTR)                 // B limb plane elems (10240)
#define GBUF (2 * APL + 2 * BPL)          // buffer elems (30720)
#define G_SMEM_B (2 * GBUF * 2)           // bytes: 122880

template<int MODE>
__global__ __launch_bounds__(256, 1) void mma_gemm(const float* __restrict__ bias,
                                                   float* __restrict__ C)
{
    extern __shared__ __nv_bfloat16 gs[];

    const int t    = threadIdx.x;
    const int lane = t & 31;
    const int wid  = t >> 5;
    const int wm   = (wid & 1) << 6;       // 0 / 64
    const int wn   = (wid >> 1) << 6;      // 0 / 64 / 128 / 192
    const int m0   = blockIdx.y * 128;
    const int n0   = blockIdx.x * 256;

    const __nv_bfloat16* Ah = (MODE == 0) ? g_xh  : g_aoh;
    const __nv_bfloat16* Al = (MODE == 0) ? g_xl  : g_aol;
    const __nv_bfloat16* Bh = (MODE == 0) ? g_wqh : g_woh;
    const __nv_bfloat16* Bl = (MODE == 0) ? g_wql : g_wol;

    const uint32_t s_base = smem_u32(gs);

    // cp.async mapping: rows r = idx>>2, 8-elem chunk c = (idx&3)<<3
#define G_LOAD(st, bf) do {                                                       \
    const int k0 = (st) * 32;                                                     \
    const uint32_t bo = s_base + (uint32_t)(bf) * (GBUF * 2);                     \
    _Pragma("unroll")                                                             \
    for (int u = 0; u < 2; u++) {          /* A: 128 rows x 4 chunks */           \
        const int idx = t + u * 256;                                              \
        const int r = idx >> 2, c = (idx & 3) << 3;                               \
        const uint32_t so = (uint32_t)(r * GSTR + c) * 2;                         \
        const size_t ga = (size_t)(m0 + r) * KD + k0 + c;                         \
        cp16(bo + so,           Ah + ga);                                         \
        cp16(bo + APL * 2 + so, Al + ga);                                         \
    }                                                                             \
    _Pragma("unroll")                                                             \
    for (int u = 0; u < 4; u++) {          /* B: 256 rows x 4 chunks */           \
        const int idx = t + u * 256;                                              \
        const int r = idx >> 2, c = (idx & 3) << 3;                               \
        const uint32_t so = (uint32_t)(r * GSTR + c) * 2;                         \
        const size_t gb = (size_t)(n0 + r) * KD + k0 + c;                         \
        cp16(bo + 4 * APL + so,           Bh + gb);                               \
        cp16(bo + 4 * APL + BPL * 2 + so, Bl + gb);                               \
    }                                                                             \
    cp_commit(); } while (0)

    // ldmatrix lane addressing
    const int a_r = wm + (lane & 15);
    const int a_c = (lane >> 4) << 3;
    const int b_r = wn + ((lane >> 4) << 3) + (lane & 7);
    const int b_c = ((lane >> 3) & 1) << 3;

    float acc[4][8][4];
    #pragma unroll
    for (int mt = 0; mt < 4; mt++)
        #pragma unroll
        for (int nt = 0; nt < 8; nt++)
            #pragma unroll
            for (int q = 0; q < 4; q++) acc[mt][nt][q] = 0.f;

    G_LOAD(0, 0);

    const int NSTEP = KD / 32;             // 32
    for (int st = 0; st < NSTEP; st++) {
        const int buf = st & 1;
        cp_wait0();                        // current buffer resident
        __syncthreads();                   // everyone done with other buffer
        if (st + 1 < NSTEP) G_LOAD(st + 1, 1 - buf);   // prefetch (overlaps compute)

        const uint32_t bo = s_base + (uint32_t)buf * (GBUF * 2);
        #pragma unroll
        for (int kk = 0; kk < 32; kk += 16) {
            uint32_t ah[4][4], al[4][4];
            #pragma unroll
            for (int mt = 0; mt < 4; mt++) {
                const uint32_t ad = bo + (uint32_t)(((a_r + mt * 16) * GSTR) + kk + a_c) * 2;
                ldsm_x4(ah[mt], ad);
                ldsm_x4(al[mt], ad + APL * 2);
            }
            #pragma unroll
            for (int half = 0; half < 2; half++) {
                uint32_t bhf[2][4], blf[2][4];
                #pragma unroll
                for (int prl = 0; prl < 2; prl++) {
                    const int pr = half * 2 + prl;
                    const uint32_t bd = bo + 4 * APL
                        + (uint32_t)(((b_r + pr * 16) * GSTR) + kk + b_c) * 2;
                    ldsm_x4(bhf[prl], bd);
                    ldsm_x4(blf[prl], bd + BPL * 2);
                }
                #pragma unroll
                for (int mt = 0; mt < 4; mt++)
                    #pragma unroll
                    for (int ntl = 0; ntl < 4; ntl++) {
                        uint32_t* B0 = &bhf[ntl >> 1][(ntl & 1) * 2];
                        uint32_t* B1 = &blf[ntl >> 1][(ntl & 1) * 2];
                        float* cc = acc[mt][half * 4 + ntl];
                        mma_bf16(cc, ah[mt], B0);
                        mma_bf16(cc, ah[mt], B1);
                        mma_bf16(cc, al[mt], B0);
                    }
            }
        }
        __syncthreads();                   // compute done before next prefetch cycle reuses
    }

    // ---- epilogue ----
    const int part = (MODE == 0) ? (n0 >> 10) : 0;
    const int e0   = n0 & 1023;
    #pragma unroll
    for (int mt = 0; mt < 4; mt++) {
        #pragma unroll
        for (int half = 0; half < 2; half++) {
            const int m = m0 + wm + mt * 16 + (lane >> 2) + half * 8;
            if (MODE == 0) {
                const int bb = m >> 10, nn = m & 1023;
                #pragma unroll
                for (int nt = 0; nt < 8; nt++) {
                    const int e  = e0 + wn + nt * 8 + (lane & 3) * 2;
                    const int hh = e >> 6, d = e & 63;
                    const size_t off = ((size_t)((bb * HEADS + hh) * NTOK + nn) << 6) + d;
                    float vx = acc[mt][nt][half * 2], vy = acc[mt][nt][half * 2 + 1];
                    uint32_t hi, lo;
                    if (part == 0) {
                        vx *= 0.125f; vy *= 0.125f;
                        split2(vx, vy, hi, lo);
                        *(uint32_t*)&g_qh[off] = hi; *(uint32_t*)&g_ql[off] = lo;
                    } else if (part == 1) {
                        split2(vx, vy, hi, lo);
                        *(uint32_t*)&g_kh[off] = hi; *(uint32_t*)&g_kl[off] = lo;
                    } else {
                        split2(vx, vy, hi, lo);
                        *(uint32_t*)&g_vh[off] = hi; *(uint32_t*)&g_vl[off] = lo;
                    }
                }
            } else {
                #pragma unroll
                for (int nt = 0; nt < 8; nt++) {
                    const int cg = n0 + wn + nt * 8 + (lane & 3) * 2;
                    const float2 b2 = *(const float2*)&bias[cg];
                    float2 v = make_float2(acc[mt][nt][half * 2] + b2.x,
                                           acc[mt][nt][half * 2 + 1] + b2.y);
                    *(float2*)&C[(size_t)m * EMB + cg] = v;
                }
            }
        }
    }
}

// ============================================================================
// Tensor-core flash attention, split-bf16 limbs everywhere. (unchanged)
// ============================================================================
#define ASTR 72
#define PLANE_B (64 * ASTR * 2)
#define ATTN_SMEM (2 * 4 * 64 * ASTR * 2 + 1024 * 4)

__global__ __launch_bounds__(256) void attn_mma(const float* __restrict__ biases)
{
    extern __shared__ __nv_bfloat16 smem[];
    float* s_bias = (float*)(smem + 2 * 4 * 64 * ASTR);

    const int t = threadIdx.x, lane = t & 31, w = t >> 5;
    const int qt = blockIdx.x, h = blockIdx.y, b = blockIdx.z;
    const int bh = b * HEADS + h;
    const int q0 = qt * 128;
    const int rw = w * 16;

    for (int i = t; i < 1024; i += 256) s_bias[i] = biases[h * 1024 + i];

    uint32_t qh[4][4], ql[4][4];
    const uint32_t qAddr = smem_u32(smem) + ((rw + (lane & 15)) * ASTR + ((lane >> 4) << 3)) * 2;
    {
        const __nv_bfloat16* qsrc = g_qh + ((size_t)bh * NTOK + q0) * 64;
        #pragma unroll
        for (int u = 0; u < 4; u++) {
            const int id = t + u * 256, r = id >> 3, ch = (id & 7) * 8;
            cp16(smem_u32(smem + r * ASTR + ch), qsrc + (size_t)r * 64 + ch);
        }
        cp_commit(); cp_wait0(); __syncthreads();
        #pragma unroll
        for (int kk = 0; kk < 4; kk++) ldsm_x4(qh[kk], qAddr + kk * 32);
        __syncthreads();

        qsrc = g_ql + ((size_t)bh * NTOK + q0) * 64;
        #pragma unroll
        for (int u = 0; u < 4; u++) {
            const int id = t + u * 256, r = id >> 3, ch = (id & 7) * 8;
            cp16(smem_u32(smem + r * ASTR + ch), qsrc + (size_t)r * 64 + ch);
        }
        cp_commit(); cp_wait0(); __syncthreads();
        #pragma unroll
        for (int kk = 0; kk < 4; kk++) ldsm_x4(ql[kk], qAddr + kk * 32);
        __syncthreads();
    }

    float s[8][4], o[8][4];
    float m0 = -1e30f, m1 = -1e30f, l0 = 0.f, l1 = 0.f;
    #pragma unroll
    for (int f = 0; f < 8; f++)
        #pragma unroll
        for (int q = 0; q < 4; q++) o[f][q] = 0.f;

    const int r_row0 = q0 + rw + (lane >> 2);
    const int xq0 = r_row0 >> 5,       yq0 = r_row0 & 31;
    const int xq1 = (r_row0 + 8) >> 5, yq1 = (r_row0 + 8) & 31;

#define LOAD_TILE(kt, bf) do {                                                   \
    _Pragma("unroll")                                                            \
    for (int u = 0; u < 8; u++) {                                                \
        const int p = u >> 1;                                                    \
        const int id = t + u * 256;                                              \
        const int rr = (id >> 3) & 63, ch = (id & 7) * 8;                        \
        const __nv_bfloat16* src = (p == 0) ? g_kh : (p == 1) ? g_kl             \
                                 : (p == 2) ? g_vh : g_vl;                       \
        cp16(smem_u32(smem + (((bf) * 4 + p) * 64 + rr) * ASTR + ch),            \
             src + ((size_t)bh * NTOK + (kt) * 64 + rr) * 64 + ch);              \
    }                                                                            \
    cp_commit(); } while (0)

    LOAD_TILE(0, 0);

    for (int kt = 0; kt < 16; kt++) {
        const int buf = kt & 1;
        if (kt < 15) { LOAD_TILE(kt + 1, 1 - buf); cp_wait1(); }
        else         { cp_wait0(); }
        __syncthreads();

        const uint32_t base = smem_u32(smem) + buf * 4 * PLANE_B;
        const uint32_t laddr = ((lane & 15) * ASTR + ((lane >> 4) << 3)) * 2;

        #pragma unroll
        for (int f = 0; f < 8; f++)
            #pragma unroll
            for (int q = 0; q < 4; q++) s[f][q] = 0.f;

        #pragma unroll
        for (int kk = 0; kk < 4; kk++) {
            #pragma unroll
            for (int ng = 0; ng < 4; ng++) {
                uint32_t kh[4], kl[4];
                const uint32_t ad = base + laddr + (ng * 16 * ASTR + kk * 16) * 2;
                ldsm_x4(kh, ad);
                ldsm_x4(kl, ad + PLANE_B);
                uint32_t bh0[2] = {kh[0], kh[2]}, bh1[2] = {kh[1], kh[3]};
                uint32_t bl0[2] = {kl[0], kl[2]}, bl1[2] = {kl[1], kl[3]};
                mma_bf16(s[2*ng],   qh[kk], bh0);
                mma_bf16(s[2*ng],   qh[kk], bl0);
                mma_bf16(s[2*ng],   ql[kk], bh0);
                mma_bf16(s[2*ng+1], qh[kk], bh1);
                mma_bf16(s[2*ng+1], qh[kk], bl1);
                mma_bf16(s[2*ng+1], ql[kk], bh1);
            }
        }

        float tm0 = -1e30f, tm1 = -1e30f;
        const int cb = kt * 64 + (lane & 3) * 2;
        #pragma unroll
        for (int f = 0; f < 8; f++) {
            const int c0 = cb + f * 8, c1 = c0 + 1;
            const int cx0 = c0 >> 5, cy0 = c0 & 31;
            const int cx1 = c1 >> 5, cy1 = c1 & 31;
            s[f][0] += s_bias[abs(xq0 - cx0) * 32 + abs(yq0 - cy0)];
            s[f][1] += s_bias[abs(xq0 - cx1) * 32 + abs(yq0 - cy1)];
            s[f][2] += s_bias[abs(xq1 - cx0) * 32 + abs(yq1 - cy0)];
            s[f][3] += s_bias[abs(xq1 - cx1) * 32 + abs(yq1 - cy1)];
            tm0 = fmaxf(tm0, fmaxf(s[f][0], s[f][1]));
            tm1 = fmaxf(tm1, fmaxf(s[f][2], s[f][3]));
        }
        tm0 = fmaxf(tm0, __shfl_xor_sync(0xffffffffu, tm0, 1));
        tm0 = fmaxf(tm0, __shfl_xor_sync(0xffffffffu, tm0, 2));
        tm1 = fmaxf(tm1, __shfl_xor_sync(0xffffffffu, tm1, 1));
        tm1 = fmaxf(tm1, __shfl_xor_sync(0xffffffffu, tm1, 2));

        const float mn0 = fmaxf(m0, tm0), mn1 = fmaxf(m1, tm1);
        const float fac0 = __expf(m0 - mn0), fac1 = __expf(m1 - mn1);
        m0 = mn0; m1 = mn1;
        l0 *= fac0; l1 *= fac1;
        #pragma unroll
        for (int f = 0; f < 8; f++) {
            s[f][0] = __expf(s[f][0] - m0); s[f][1] = __expf(s[f][1] - m0);
            s[f][2] = __expf(s[f][2] - m1); s[f][3] = __expf(s[f][3] - m1);
            l0 += s[f][0] + s[f][1];
            l1 += s[f][2] + s[f][3];
            o[f][0] *= fac0; o[f][1] *= fac0; o[f][2] *= fac1; o[f][3] *= fac1;
        }

        const uint32_t vbase = base + 2 * PLANE_B;
        #pragma unroll
        for (int kk2 = 0; kk2 < 4; kk2++) {
            uint32_t ah[4], al[4];
            split2(s[2*kk2][0],   s[2*kk2][1],   ah[0], al[0]);
            split2(s[2*kk2][2],   s[2*kk2][3],   ah[1], al[1]);
            split2(s[2*kk2+1][0], s[2*kk2+1][1], ah[2], al[2]);
            split2(s[2*kk2+1][2], s[2*kk2+1][3], ah[3], al[3]);
            #pragma unroll
            for (int dg = 0; dg < 4; dg++) {
                const int nf = dg * 2;
                uint32_t vh[4], vl[4];
                const uint32_t ad = vbase + laddr + (kk2 * 16 * ASTR + dg * 16) * 2;
                ldsm_x4_t(vh, ad);
                ldsm_x4_t(vl, ad + PLANE_B);
                uint32_t bh0[2] = {vh[0], vh[1]}, bh1[2] = {vh[2], vh[3]};
                uint32_t bl0[2] = {vl[0], vl[1]}, bl1[2] = {vl[2], vl[3]};
                mma_bf16(o[nf],   ah, bh0);
                mma_bf16(o[nf],   ah, bl0);
                mma_bf16(o[nf],   al, bh0);
                mma_bf16(o[nf+1], ah, bh1);
                mma_bf16(o[nf+1], ah, bl1);
                mma_bf16(o[nf+1], al, bh1);
            }
        }
        __syncthreads();
    }

    l0 += __shfl_xor_sync(0xffffffffu, l0, 1);
    l0 += __shfl_xor_sync(0xffffffffu, l0, 2);
    l1 += __shfl_xor_sync(0xffffffffu, l1, 1);
    l1 += __shfl_xor_sync(0xffffffffu, l1, 2);
    const float inv0 = 1.0f / l0, inv1 = 1.0f / l1;

    const size_t rbase0 = ((size_t)(b * NTOK + r_row0)) * EMB + h * 64;
    const size_t rbase1 = rbase0 + (size_t)8 * EMB;
    #pragma unroll
    for (int f = 0; f < 8; f++) {
        const int d = f * 8 + (lane & 3) * 2;
        uint32_t hi, lo;
        split2(o[f][0] * inv0, o[f][1] * inv0, hi, lo);
        *(uint32_t*)&g_aoh[rbase0 + d] = hi;
        *(uint32_t*)&g_aol[rbase0 + d] = lo;
        split2(o[f][2] * inv1, o[f][3] * inv1, hi, lo);
        *(uint32_t*)&g_aoh[rbase1 + d] = hi;
        *(uint32_t*)&g_aol[rbase1 + d] = lo;
    }
}

// ============================================================================
extern "C" void kernel_launch(void* const* d_in, const int* in_sizes, int n_in,
                              void* d_out, int out_size)
{
    const float* x     = (const float*)d_in[0];
    const float* Wqkv  = (const float*)d_in[1];
    const float* ab    = (const float*)d_in[2];
    // d_in[3] = bias_idxs : not needed (idx = |dx|*32 + |dy| analytically)
    const float* Wout  = (const float*)d_in[4];
    const float* bout  = (const float*)d_in[5];
    float* out = (float*)d_out;

    cudaFuncSetAttribute(attn_mma, cudaFuncAttributeMaxDynamicSharedMemorySize,
                         ATTN_SMEM);
    cudaFuncSetAttribute(mma_gemm<0>, cudaFuncAttributeMaxDynamicSharedMemorySize,
                         G_SMEM_B);
    cudaFuncSetAttribute(mma_gemm<1>, cudaFuncAttributeMaxDynamicSharedMemorySize,
                         G_SMEM_B);

    convert_kernel<<<8192*1024/1024, 256>>>(x,    0, 8192*1024);
    convert_kernel<<<3072*1024/1024, 256>>>(Wqkv, 1, 3072*1024);
    convert_kernel<<<1024*1024/1024, 256>>>(Wout, 2, 1024*1024);

    mma_gemm<0><<<dim3(3072/256, 8192/128), 256, G_SMEM_B>>>(nullptr, nullptr);
    attn_mma<<<dim3(NTOK/128, HEADS, BATCH), 256, ATTN_SMEM>>>(ab);
    mma_gemm<1><<<dim3(1024/256, 8192/128), 256, G_SMEM_B>>>(bout, out);
}

// round 9
// speedup vs baseline: 3.6450x; 1.3950x over previous
#include <cuda_runtime.h>
#include <cuda_fp16.h>
#include <cstdint>

#define BATCH 8
#define HEADS 16
#define NTOK  1024
#define DHEAD 64
#define EMB   1024
#define KD    1024

// ---- scratch (allocation-free rule: __device__ globals) ----
// q split into fp16 hi/lo limbs; k, v single fp16. layout [b,h,n,d]
__device__ __half g_qh[BATCH*HEADS*NTOK*DHEAD];
__device__ __half g_ql[BATCH*HEADS*NTOK*DHEAD];
__device__ __half g_k [BATCH*HEADS*NTOK*DHEAD];
__device__ __half g_v [BATCH*HEADS*NTOK*DHEAD];

__device__ __half g_xh [8192*1024];   // x limbs (A side of QKV gemm)
__device__ __half g_xl [8192*1024];
__device__ __half g_wq [3072*1024];   // Wqkv single fp16 (B side)
__device__ __half g_wo [1024*1024];   // Wout single fp16
__device__ __half g_aoh[8192*1024];   // attn-out limbs (A side of out-proj)
__device__ __half g_aol[8192*1024];

// ---------------------------------------------------------------------------
__device__ __forceinline__ uint32_t smem_u32(const void* p) {
    return (uint32_t)__cvta_generic_to_shared(p);
}
__device__ __forceinline__ uint32_t pack2h(float x, float y) {
    __half2 t = __floats2half2_rn(x, y);
    return *reinterpret_cast<uint32_t*>(&t);
}
__device__ __forceinline__ void split2h(float x, float y, uint32_t& hi, uint32_t& lo) {
    __half hx = __float2half_rn(x), hy = __float2half_rn(y);
    __half2 h = __halves2half2(hx, hy);
    hi = *reinterpret_cast<uint32_t*>(&h);
    lo = pack2h(x - __half2float(hx), y - __half2float(hy));
}
__device__ __forceinline__ void ldsm_x4(uint32_t* r, uint32_t addr) {
    asm volatile("ldmatrix.sync.aligned.m8n8.x4.shared.b16 {%0,%1,%2,%3},[%4];"
                 : "=r"(r[0]), "=r"(r[1]), "=r"(r[2]), "=r"(r[3]) : "r"(addr));
}
__device__ __forceinline__ void ldsm_x4_t(uint32_t* r, uint32_t addr) {
    asm volatile("ldmatrix.sync.aligned.m8n8.x4.trans.shared.b16 {%0,%1,%2,%3},[%4];"
                 : "=r"(r[0]), "=r"(r[1]), "=r"(r[2]), "=r"(r[3]) : "r"(addr));
}
__device__ __forceinline__ void mma_f16(float* c, const uint32_t* a, const uint32_t* b) {
    asm volatile("mma.sync.aligned.m16n8k16.row.col.f32.f16.f16.f32 "
                 "{%0,%1,%2,%3},{%4,%5,%6,%7},{%8,%9},{%0,%1,%2,%3};"
                 : "+f"(c[0]), "+f"(c[1]), "+f"(c[2]), "+f"(c[3])
                 : "r"(a[0]), "r"(a[1]), "r"(a[2]), "r"(a[3]), "r"(b[0]), "r"(b[1]));
}
__device__ __forceinline__ void cp16(uint32_t dst, const void* src) {
    asm volatile("cp.async.ca.shared.global [%0],[%1],16;" :: "r"(dst), "l"(src));
}
__device__ __forceinline__ void cp_commit() { asm volatile("cp.async.commit_group;"); }
__device__ __forceinline__ void cp_wait0() { asm volatile("cp.async.wait_group 0;"); }
__device__ __forceinline__ void cp_wait1() { asm volatile("cp.async.wait_group 1;"); }

// ---------------------------------------------------------------------------
// fp32 -> fp16 conversion. which 0: x -> split limbs; 1: Wqkv single; 2: Wout single
// ---------------------------------------------------------------------------
__global__ __launch_bounds__(256) void convert_kernel(const float* __restrict__ src,
                                                      int which, int n)
{
    int i = (blockIdx.x * 256 + threadIdx.x) * 4;
    if (i >= n) return;
    float4 v = *(const float4*)(src + i);
    if (which == 0) {
        uint2 ph, pl;
        split2h(v.x, v.y, ph.x, pl.x);
        split2h(v.z, v.w, ph.y, pl.y);
        *(uint2*)&g_xh[i] = ph;
        *(uint2*)&g_xl[i] = pl;
    } else {
        uint2 p;
        p.x = pack2h(v.x, v.y);
        p.y = pack2h(v.z, v.w);
        if (which == 1) *(uint2*)&g_wq[i] = p;
        else            *(uint2*)&g_wo[i] = p;
    }
}

// ---------------------------------------------------------------------------
// 2-product fp16 HMMA GEMM: C[m,c] = (Ah+Al)(m,:) . B(c,:)  = AhB + AlB
// Block 128x256, 256 thr (8 warps as 2M x 4N), warp tile 64x64, K-step 32,
// cp.async double-buffered.
// MODE 0: A=x limbs, B=Wqkv -> q limbs / k / v  (q *= 0.125)
// MODE 1: A=attn-out limbs, B=Wout -> +bias -> C (fp32)
// ---------------------------------------------------------------------------
#define GSTR 40                               // smem row stride (elems)
#define APLB (128 * GSTR * 2)                 // A limb plane bytes (10240)
#define BPLB (256 * GSTR * 2)                 // B plane bytes (20480)
#define BUFB (2 * APLB + BPLB)                // buffer bytes (40960)
#define G_SMEM_B (2 * BUFB)                   // 81920

template<int MODE>
__global__ __launch_bounds__(256, 1) void mma_gemm(const float* __restrict__ bias,
                                                   float* __restrict__ C)
{
    extern __shared__ __half gs[];

    const int t    = threadIdx.x;
    const int lane = t & 31;
    const int wid  = t >> 5;
    const int wm   = (wid & 1) << 6;
    const int wn   = (wid >> 1) << 6;
    const int m0   = blockIdx.y * 128;
    const int n0   = blockIdx.x * 256;

    const __half* Ah = (MODE == 0) ? g_xh : g_aoh;
    const __half* Al = (MODE == 0) ? g_xl : g_aol;
    const __half* Bs = (MODE == 0) ? g_wq : g_wo;

    const uint32_t s_base = smem_u32(gs);

#define G_LOAD(st, bf) do {                                                       \
    const int k0 = (st) * 32;                                                     \
    const uint32_t bo = s_base + (uint32_t)(bf) * BUFB;                           \
    _Pragma("unroll")                                                             \
    for (int u = 0; u < 2; u++) {          /* A: 128 rows x 4 chunks, 2 limbs */  \
        const int idx = t + u * 256;                                              \
        const int r = idx >> 2, c = (idx & 3) << 3;                               \
        const uint32_t so = (uint32_t)(r * GSTR + c) * 2;                         \
        const size_t ga = (size_t)(m0 + r) * KD + k0 + c;                         \
        cp16(bo + so,        Ah + ga);                                            \
        cp16(bo + APLB + so, Al + ga);                                            \
    }                                                                             \
    _Pragma("unroll")                                                             \
    for (int u = 0; u < 4; u++) {          /* B: 256 rows x 4 chunks, 1 plane */  \
        const int idx = t + u * 256;                                              \
        const int r = idx >> 2, c = (idx & 3) << 3;                               \
        const uint32_t so = (uint32_t)(r * GSTR + c) * 2;                         \
        const size_t gb = (size_t)(n0 + r) * KD + k0 + c;                         \
        cp16(bo + 2 * APLB + so, Bs + gb);                                        \
    }                                                                             \
    cp_commit(); } while (0)

    const int a_r = wm + (lane & 15);
    const int a_c = (lane >> 4) << 3;
    const int b_r = wn + ((lane >> 4) << 3) + (lane & 7);
    const int b_c = ((lane >> 3) & 1) << 3;

    float acc[4][8][4];
    #pragma unroll
    for (int mt = 0; mt < 4; mt++)
        #pragma unroll
        for (int nt = 0; nt < 8; nt++)
            #pragma unroll
            for (int q = 0; q < 4; q++) acc[mt][nt][q] = 0.f;

    G_LOAD(0, 0);

    const int NSTEP = KD / 32;
    for (int st = 0; st < NSTEP; st++) {
        const int buf = st & 1;
        cp_wait0();
        __syncthreads();
        if (st + 1 < NSTEP) G_LOAD(st + 1, 1 - buf);

        const uint32_t bo = s_base + (uint32_t)buf * BUFB;
        #pragma unroll
        for (int kk = 0; kk < 32; kk += 16) {
            uint32_t ah[4][4], al[4][4];
            #pragma unroll
            for (int mt = 0; mt < 4; mt++) {
                const uint32_t ad = bo + (uint32_t)(((a_r + mt * 16) * GSTR) + kk + a_c) * 2;
                ldsm_x4(ah[mt], ad);
                ldsm_x4(al[mt], ad + APLB);
            }
            #pragma unroll
            for (int half = 0; half < 2; half++) {
                uint32_t bhf[2][4];
                #pragma unroll
                for (int prl = 0; prl < 2; prl++) {
                    const int pr = half * 2 + prl;
                    const uint32_t bd = bo + 2 * APLB
                        + (uint32_t)(((b_r + pr * 16) * GSTR) + kk + b_c) * 2;
                    ldsm_x4(bhf[prl], bd);
                }
                #pragma unroll
                for (int mt = 0; mt < 4; mt++)
                    #pragma unroll
                    for (int ntl = 0; ntl < 4; ntl++) {
                        uint32_t* B0 = &bhf[ntl >> 1][(ntl & 1) * 2];
                        float* cc = acc[mt][half * 4 + ntl];
                        mma_f16(cc, ah[mt], B0);
                        mma_f16(cc, al[mt], B0);
                    }
            }
        }
        __syncthreads();
    }

    // ---- epilogue ----
    const int part = (MODE == 0) ? (n0 >> 10) : 0;
    const int e0   = n0 & 1023;
    #pragma unroll
    for (int mt = 0; mt < 4; mt++) {
        #pragma unroll
        for (int half = 0; half < 2; half++) {
            const int m = m0 + wm + mt * 16 + (lane >> 2) + half * 8;
            if (MODE == 0) {
                const int bb = m >> 10, nn = m & 1023;
                #pragma unroll
                for (int nt = 0; nt < 8; nt++) {
                    const int e  = e0 + wn + nt * 8 + (lane & 3) * 2;
                    const int hh = e >> 6, d = e & 63;
                    const size_t off = ((size_t)((bb * HEADS + hh) * NTOK + nn) << 6) + d;
                    float vx = acc[mt][nt][half * 2], vy = acc[mt][nt][half * 2 + 1];
                    if (part == 0) {
                        uint32_t hi, lo;
                        split2h(vx * 0.125f, vy * 0.125f, hi, lo);
                        *(uint32_t*)&g_qh[off] = hi;
                        *(uint32_t*)&g_ql[off] = lo;
                    } else if (part == 1) {
                        *(uint32_t*)&g_k[off] = pack2h(vx, vy);
                    } else {
                        *(uint32_t*)&g_v[off] = pack2h(vx, vy);
                    }
                }
            } else {
                #pragma unroll
                for (int nt = 0; nt < 8; nt++) {
                    const int cg = n0 + wn + nt * 8 + (lane & 3) * 2;
                    const float2 b2 = *(const float2*)&bias[cg];
                    float2 v = make_float2(acc[mt][nt][half * 2] + b2.x,
                                           acc[mt][nt][half * 2 + 1] + b2.y);
                    *(float2*)&C[(size_t)m * EMB + cg] = v;
                }
            }
        }
    }
}

// ============================================================================
// fp16 2-product flash attention.
// Block = 128 queries (8 warps x m16), 16 key tiles of 64.
// smem: [2 bufs][K plane, V plane][64 rows][72 fp16] + bias[1024] f32
// S = Qh K + Ql K ; O += Ph V + Pl V  (P split in-register)
// ============================================================================
#define ASTR 72
#define PLNB (64 * ASTR * 2)                  // plane bytes (9216)
#define ATTN_SMEM (2 * 2 * PLNB + 1024 * 4)   // 40960

__global__ __launch_bounds__(256) void attn_mma(const float* __restrict__ biases)
{
    extern __shared__ __half smem[];
    float* s_bias = (float*)((char*)smem + 2 * 2 * PLNB);

    const int t = threadIdx.x, lane = t & 31, w = t >> 5;
    const int qt = blockIdx.x, h = blockIdx.y, b = blockIdx.z;
    const int bh = b * HEADS + h;
    const int q0 = qt * 128;
    const int rw = w * 16;

    for (int i = t; i < 1024; i += 256) s_bias[i] = biases[h * 1024 + i];

    // ---- Q fragment preload (hi, lo limbs), staged through smem ----
    uint32_t qh[4][4], ql[4][4];
    const uint32_t qAddr = smem_u32(smem) + ((rw + (lane & 15)) * ASTR + ((lane >> 4) << 3)) * 2;
    {
        const __half* qsrc = g_qh + ((size_t)bh * NTOK + q0) * 64;
        #pragma unroll
        for (int u = 0; u < 4; u++) {
            const int id = t + u * 256, r = id >> 3, ch = (id & 7) * 8;
            cp16(smem_u32(smem + r * ASTR + ch), qsrc + (size_t)r * 64 + ch);
        }
        cp_commit(); cp_wait0(); __syncthreads();
        #pragma unroll
        for (int kk = 0; kk < 4; kk++) ldsm_x4(qh[kk], qAddr + kk * 32);
        __syncthreads();

        qsrc = g_ql + ((size_t)bh * NTOK + q0) * 64;
        #pragma unroll
        for (int u = 0; u < 4; u++) {
            const int id = t + u * 256, r = id >> 3, ch = (id & 7) * 8;
            cp16(smem_u32(smem + r * ASTR + ch), qsrc + (size_t)r * 64 + ch);
        }
        cp_commit(); cp_wait0(); __syncthreads();
        #pragma unroll
        for (int kk = 0; kk < 4; kk++) ldsm_x4(ql[kk], qAddr + kk * 32);
        __syncthreads();
    }

    float s[8][4], o[8][4];
    float m0 = -1e30f, m1 = -1e30f, l0 = 0.f, l1 = 0.f;
    #pragma unroll
    for (int f = 0; f < 8; f++)
        #pragma unroll
        for (int q = 0; q < 4; q++) o[f][q] = 0.f;

    const int r_row0 = q0 + rw + (lane >> 2);
    const int xq0 = r_row0 >> 5,       yq0 = r_row0 & 31;
    const int xq1 = (r_row0 + 8) >> 5, yq1 = (r_row0 + 8) & 31;

#define LOAD_TILE(kt, bf) do {                                                   \
    _Pragma("unroll")                                                            \
    for (int u = 0; u < 4; u++) {                                                \
        const int p = u >> 1;                                                    \
        const int id = t + u * 256;                                              \
        const int rr = (id >> 3) & 63, ch = (id & 7) * 8;                        \
        const __half* src = (p == 0) ? g_k : g_v;                                \
        cp16(smem_u32(smem + (((bf) * 2 + p) * 64 + rr) * ASTR + ch),            \
             src + ((size_t)bh * NTOK + (kt) * 64 + rr) * 64 + ch);              \
    }                                                                            \
    cp_commit(); } while (0)

    LOAD_TILE(0, 0);

    for (int kt = 0; kt < 16; kt++) {
        const int buf = kt & 1;
        if (kt < 15) { LOAD_TILE(kt + 1, 1 - buf); cp_wait1(); }
        else         { cp_wait0(); }
        __syncthreads();

        const uint32_t base = smem_u32(smem) + buf * 2 * PLNB;
        const uint32_t laddr = ((lane & 15) * ASTR + ((lane >> 4) << 3)) * 2;

        // ---- S = Qh K + Ql K ----
        #pragma unroll
        for (int f = 0; f < 8; f++)
            #pragma unroll
            for (int q = 0; q < 4; q++) s[f][q] = 0.f;

        #pragma unroll
        for (int kk = 0; kk < 4; kk++) {
            #pragma unroll
            for (int ng = 0; ng < 4; ng++) {
                uint32_t kf[4];
                ldsm_x4(kf, base + laddr + (ng * 16 * ASTR + kk * 16) * 2);
                uint32_t b0[2] = {kf[0], kf[2]}, b1[2] = {kf[1], kf[3]};
                mma_f16(s[2*ng],   qh[kk], b0);
                mma_f16(s[2*ng],   ql[kk], b0);
                mma_f16(s[2*ng+1], qh[kk], b1);
                mma_f16(s[2*ng+1], ql[kk], b1);
            }
        }

        // ---- bias + online softmax ----
        float tm0 = -1e30f, tm1 = -1e30f;
        const int cb = kt * 64 + (lane & 3) * 2;
        #pragma unroll
        for (int f = 0; f < 8; f++) {
            const int c0 = cb + f * 8, c1 = c0 + 1;
            const int cx0 = c0 >> 5, cy0 = c0 & 31;
            const int cx1 = c1 >> 5, cy1 = c1 & 31;
            s[f][0] += s_bias[abs(xq0 - cx0) * 32 + abs(yq0 - cy0)];
            s[f][1] += s_bias[abs(xq0 - cx1) * 32 + abs(yq0 - cy1)];
            s[f][2] += s_bias[abs(xq1 - cx0) * 32 + abs(yq1 - cy0)];
            s[f][3] += s_bias[abs(xq1 - cx1) * 32 + abs(yq1 - cy1)];
            tm0 = fmaxf(tm0, fmaxf(s[f][0], s[f][1]));
            tm1 = fmaxf(tm1, fmaxf(s[f][2], s[f][3]));
        }
        tm0 = fmaxf(tm0, __shfl_xor_sync(0xffffffffu, tm0, 1));
        tm0 = fmaxf(tm0, __shfl_xor_sync(0xffffffffu, tm0, 2));
        tm1 = fmaxf(tm1, __shfl_xor_sync(0xffffffffu, tm1, 1));
        tm1 = fmaxf(tm1, __shfl_xor_sync(0xffffffffu, tm1, 2));

        const float mn0 = fmaxf(m0, tm0), mn1 = fmaxf(m1, tm1);
        const float fac0 = __expf(m0 - mn0), fac1 = __expf(m1 - mn1);
        m0 = mn0; m1 = mn1;
        l0 *= fac0; l1 *= fac1;
        #pragma unroll
        for (int f = 0; f < 8; f++) {
            s[f][0] = __expf(s[f][0] - m0); s[f][1] = __expf(s[f][1] - m0);
            s[f][2] = __expf(s[f][2] - m1); s[f][3] = __expf(s[f][3] - m1);
            l0 += s[f][0] + s[f][1];
            l1 += s[f][2] + s[f][3];
            o[f][0] *= fac0; o[f][1] *= fac0; o[f][2] *= fac1; o[f][3] *= fac1;
        }

        // ---- O += Ph V + Pl V (P split in-register) ----
        const uint32_t vbase = base + PLNB;
        #pragma unroll
        for (int kk2 = 0; kk2 < 4; kk2++) {
            uint32_t ah[4], al[4];
            split2h(s[2*kk2][0],   s[2*kk2][1],   ah[0], al[0]);
            split2h(s[2*kk2][2],   s[2*kk2][3],   ah[1], al[1]);
            split2h(s[2*kk2+1][0], s[2*kk2+1][1], ah[2], al[2]);
            split2h(s[2*kk2+1][2], s[2*kk2+1][3], ah[3], al[3]);
            #pragma unroll
            for (int dg = 0; dg < 4; dg++) {
                const int nf = dg * 2;
                uint32_t vf[4];
                ldsm_x4_t(vf, vbase + laddr + (kk2 * 16 * ASTR + dg * 16) * 2);
                uint32_t b0[2] = {vf[0], vf[1]}, b1[2] = {vf[2], vf[3]};
                mma_f16(o[nf],   ah, b0);
                mma_f16(o[nf],   al, b0);
                mma_f16(o[nf+1], ah, b1);
                mma_f16(o[nf+1], al, b1);
            }
        }
        __syncthreads();
    }

    // ---- epilogue: normalize, write attn-out fp16 limbs ----
    l0 += __shfl_xor_sync(0xffffffffu, l0, 1);
    l0 += __shfl_xor_sync(0xffffffffu, l0, 2);
    l1 += __shfl_xor_sync(0xffffffffu, l1, 1);
    l1 += __shfl_xor_sync(0xffffffffu, l1, 2);
    const float inv0 = 1.0f / l0, inv1 = 1.0f / l1;

    const size_t rbase0 = ((size_t)(b * NTOK + r_row0)) * EMB + h * 64;
    const size_t rbase1 = rbase0 + (size_t)8 * EMB;
    #pragma unroll
    for (int f = 0; f < 8; f++) {
        const int d = f * 8 + (lane & 3) * 2;
        uint32_t hi, lo;
        split2h(o[f][0] * inv0, o[f][1] * inv0, hi, lo);
        *(uint32_t*)&g_aoh[rbase0 + d] = hi;
        *(uint32_t*)&g_aol[rbase0 + d] = lo;
        split2h(o[f][2] * inv1, o[f][3] * inv1, hi, lo);
        *(uint32_t*)&g_aoh[rbase1 + d] = hi;
        *(uint32_t*)&g_aol[rbase1 + d] = lo;
    }
}

// ============================================================================
extern "C" void kernel_launch(void* const* d_in, const int* in_sizes, int n_in,
                              void* d_out, int out_size)
{
    const float* x     = (const float*)d_in[0];
    const float* Wqkv  = (const float*)d_in[1];
    const float* ab    = (const float*)d_in[2];
    // d_in[3] = bias_idxs : not needed (idx = |dx|*32 + |dy| analytically)
    const float* Wout  = (const float*)d_in[4];
    const float* bout  = (const float*)d_in[5];
    float* out = (float*)d_out;

    cudaFuncSetAttribute(attn_mma, cudaFuncAttributeMaxDynamicSharedMemorySize,
                         ATTN_SMEM);
    cudaFuncSetAttribute(mma_gemm<0>, cudaFuncAttributeMaxDynamicSharedMemorySize,
                         G_SMEM_B);
    cudaFuncSetAttribute(mma_gemm<1>, cudaFuncAttributeMaxDynamicSharedMemorySize,
                         G_SMEM_B);

    convert_kernel<<<8192*1024/1024, 256>>>(x,    0, 8192*1024);
    convert_kernel<<<3072*1024/1024, 256>>>(Wqkv, 1, 3072*1024);
    convert_kernel<<<1024*1024/1024, 256>>>(Wout, 2, 1024*1024);

    mma_gemm<0><<<dim3(3072/256, 8192/128), 256, G_SMEM_B>>>(nullptr, nullptr);
    attn_mma<<<dim3(NTOK/128, HEADS, BATCH), 256, ATTN_SMEM>>>(ab);
    mma_gemm<1><<<dim3(1024/256, 8192/128), 256, G_SMEM_B>>>(bout, out);
}